// round 13
// baseline (speedup 1.0000x reference)
#include <cuda_runtime.h>
#include <cuda_bf16.h>
#include <math.h>

#define T_LEN 4096
#define E_DIM 1024
#define H_DIM 512
#define G4H   2048     // 4*H
#define UPB   16       // hidden units per recurrence block
#define TAGS  5
#define START_TAG 3
#define STOP_TAG  4
#define SENT  2.0f     // impossible h value (|h| < 1 strictly)
#define BURN  96       // burn-in steps (contraction ~0.55^96 ~ 1e-25)
#define NSTEP 1096     // uniform steps per chunk (c0: 1096; c1-3: 96+1000)
#define BUFSZ ((BURN + 1) * H_DIM)   // private burn scratch per (dir,chunk>0)

// ---------------- scratch (device globals; no runtime allocation) -------------
__device__ float g_Gf[(size_t)T_LEN * G4H];          // gates fwd
__device__ float g_Gb[(size_t)T_LEN * G4H];          // gates bwd-scan
__device__ float g_hsf[(size_t)(T_LEN + 1) * H_DIM]; // h traj fwd (row0 = h0)
__device__ float g_hsb[(size_t)(T_LEN + 1) * H_DIM]; // h traj bwd-scan
__device__ float g_hp[6 * BUFSZ];                    // burn scratch (dir*3 + chunk-1)
__device__ float g_feats[T_LEN * TAGS];

// ---------------- helpers -----------------------------------------------------
__device__ __forceinline__ float2 ldrg2(const float* p) {
    unsigned long long u;
    asm volatile("ld.relaxed.gpu.global.b64 %0, [%1];" : "=l"(u) : "l"(p));
    float2 v;
    v.x = __uint_as_float((unsigned)(u & 0xFFFFFFFFull));
    v.y = __uint_as_float((unsigned)(u >> 32));
    return v;
}
__device__ __forceinline__ void strg(float* p, float v) {
    asm volatile("st.relaxed.gpu.global.f32 [%0], %1;" :: "l"(p), "f"(v) : "memory");
}
__device__ __forceinline__ unsigned sm_u32(const void* p) {
    unsigned r;
    asm("{ .reg .u64 t; cvta.to.shared.u64 t, %1; cvt.u32.u64 %0, t; }"
        : "=r"(r) : "l"(p));
    return r;
}
__device__ __forceinline__ void ldsm4(unsigned r[4], unsigned addr) {
    asm volatile("ldmatrix.sync.aligned.m8n8.x4.shared.b16 {%0,%1,%2,%3}, [%4];"
                 : "=r"(r[0]), "=r"(r[1]), "=r"(r[2]), "=r"(r[3]) : "r"(addr));
}
__device__ __forceinline__ void mma16816(float d[4], const unsigned a[4],
                                         unsigned b0, unsigned b1) {
    asm volatile(
        "mma.sync.aligned.m16n8k16.row.col.f32.bf16.bf16.f32 "
        "{%0,%1,%2,%3}, {%4,%5,%6,%7}, {%8,%9}, {%0,%1,%2,%3};"
        : "+f"(d[0]), "+f"(d[1]), "+f"(d[2]), "+f"(d[3])
        : "r"(a[0]), "r"(a[1]), "r"(a[2]), "r"(a[3]), "r"(b0), "r"(b1));
}

// ---------------- setup: sentinel-fill h trajectories + burn scratch ----------
__global__ void setup_kernel(const float* __restrict__ h0) {
    size_t i = (size_t)blockIdx.x * blockDim.x + threadIdx.x;
    const float4 s4 = make_float4(SENT, SENT, SENT, SENT);
    const float4 z4 = make_float4(0.f, 0.f, 0.f, 0.f);
    size_t nH4 = (size_t)T_LEN * H_DIM / 4;        // 524,288
    if (i < nH4) {
        ((float4*)(g_hsf + H_DIM))[i] = s4;
        ((float4*)(g_hsb + H_DIM))[i] = s4;
    }
    const int perBuf = (BURN * H_DIM) / 4;         // 12,288
    if (i < 6 * perBuf) {                          // burn rows 1..96 sentinel
        int buf = (int)(i / perBuf);
        int idx = (int)(i % perBuf);
        ((float4*)(g_hp + buf * BUFSZ + H_DIM))[idx] = s4;
    }
    if (i < 6 * (H_DIM / 4)) {                     // burn row 0 = zero state
        int buf = (int)(i / (H_DIM / 4));
        int idx = (int)(i % (H_DIM / 4));
        ((float4*)(g_hp + buf * BUFSZ))[idx] = z4;
    }
    if (i < H_DIM) {
        g_hsf[i] = h0[i];
        g_hsb[i] = h0[H_DIM + i];
    }
}

// ---------------- gate GEMM: bf16 tensor cores (frozen, proven) ----------------
#define GPITCH 40

__global__ __launch_bounds__(256) void gemm_bf16(
    const int* __restrict__ sent, const float* __restrict__ embed,
    const float* __restrict__ Wf, const float* __restrict__ bf,
    const float* __restrict__ Wb, const float* __restrict__ bb)
{
    const int dir = blockIdx.z;
    const float* W    = dir ? Wb : Wf;
    const float* bias = dir ? bb : bf;
    float* G          = dir ? g_Gb : g_Gf;

    __shared__ __align__(16) unsigned short smA[128 * GPITCH];
    __shared__ __align__(16) unsigned short smB[128 * GPITCH];
    __shared__ int sRow[128];

    const int tid = threadIdx.x;
    const int m0 = blockIdx.y * 128;
    const int n0 = blockIdx.x * 128;

    if (tid < 128) {
        int t = m0 + tid;
        sRow[tid] = dir ? sent[T_LEN - 1 - t] : sent[t];
    }
    __syncthreads();

    const int srow = tid >> 1;
    const int sseg = tid & 1;
    const float* aSrc = embed + (size_t)sRow[srow] * E_DIM + sseg * 16;
    const float* bSrc = W + (size_t)(n0 + srow) * E_DIM + sseg * 16;
    unsigned short* aDst = &smA[srow * GPITCH + sseg * 16];
    unsigned short* bDst = &smB[srow * GPITCH + sseg * 16];

    const int warpId = tid >> 5;
    const int lane   = tid & 31;
    const int mbase  = (warpId & 3) * 32;
    const int nbase  = (warpId >> 2) * 64;
    const int quad   = lane >> 3;
    const int rl     = lane & 7;
    const unsigned smA0 = sm_u32(smA);
    const unsigned smB0 = sm_u32(smB);

    float d[2][8][4];
#pragma unroll
    for (int i = 0; i < 2; i++)
#pragma unroll
        for (int j = 0; j < 8; j++)
#pragma unroll
            for (int q = 0; q < 4; q++) d[i][j][q] = 0.f;

    for (int kt = 0; kt < E_DIM; kt += 32) {
        {
            float4 v0 = *(const float4*)(aSrc + kt);
            float4 v1 = *(const float4*)(aSrc + kt + 4);
            float4 v2 = *(const float4*)(aSrc + kt + 8);
            float4 v3 = *(const float4*)(aSrc + kt + 12);
            __nv_bfloat162 p[8];
            p[0] = __floats2bfloat162_rn(v0.x, v0.y);
            p[1] = __floats2bfloat162_rn(v0.z, v0.w);
            p[2] = __floats2bfloat162_rn(v1.x, v1.y);
            p[3] = __floats2bfloat162_rn(v1.z, v1.w);
            p[4] = __floats2bfloat162_rn(v2.x, v2.y);
            p[5] = __floats2bfloat162_rn(v2.z, v2.w);
            p[6] = __floats2bfloat162_rn(v3.x, v3.y);
            p[7] = __floats2bfloat162_rn(v3.z, v3.w);
            *(uint4*)(aDst)     = *(uint4*)&p[0];
            *(uint4*)(aDst + 8) = *(uint4*)&p[4];

            v0 = *(const float4*)(bSrc + kt);
            v1 = *(const float4*)(bSrc + kt + 4);
            v2 = *(const float4*)(bSrc + kt + 8);
            v3 = *(const float4*)(bSrc + kt + 12);
            p[0] = __floats2bfloat162_rn(v0.x, v0.y);
            p[1] = __floats2bfloat162_rn(v0.z, v0.w);
            p[2] = __floats2bfloat162_rn(v1.x, v1.y);
            p[3] = __floats2bfloat162_rn(v1.z, v1.w);
            p[4] = __floats2bfloat162_rn(v2.x, v2.y);
            p[5] = __floats2bfloat162_rn(v2.z, v2.w);
            p[6] = __floats2bfloat162_rn(v3.x, v3.y);
            p[7] = __floats2bfloat162_rn(v3.z, v3.w);
            *(uint4*)(bDst)     = *(uint4*)&p[0];
            *(uint4*)(bDst + 8) = *(uint4*)&p[4];
        }
        __syncthreads();

#pragma unroll
        for (int s = 0; s < 2; s++) {
            unsigned afr[2][4], bfr[4][4];
#pragma unroll
            for (int i = 0; i < 2; i++) {
                int row = mbase + i * 16 + rl + ((quad & 1) << 3);
                int col = s * 16 + ((quad & 2) << 2);
                ldsm4(afr[i], smA0 + 2 * (row * GPITCH + col));
            }
#pragma unroll
            for (int j = 0; j < 4; j++) {
                int row = nbase + j * 16 + rl + ((quad & 2) << 2);
                int col = s * 16 + ((quad & 1) << 3);
                ldsm4(bfr[j], smB0 + 2 * (row * GPITCH + col));
            }
#pragma unroll
            for (int i = 0; i < 2; i++)
#pragma unroll
                for (int j = 0; j < 4; j++) {
                    mma16816(d[i][2 * j],     afr[i], bfr[j][0], bfr[j][1]);
                    mma16816(d[i][2 * j + 1], afr[i], bfr[j][2], bfr[j][3]);
                }
        }
        __syncthreads();
    }

    const int gl = lane >> 2;
    const int lc = (lane & 3) * 2;
#pragma unroll
    for (int i = 0; i < 2; i++) {
        int r0 = m0 + mbase + i * 16 + gl;
        int r1 = r0 + 8;
#pragma unroll
        for (int jj = 0; jj < 8; jj++) {
            int col = n0 + nbase + jj * 8 + lc;
            float b0 = bias[col], b1 = bias[col + 1];
            float2 v0 = make_float2(d[i][jj][0] + b0, d[i][jj][1] + b1);
            float2 v1 = make_float2(d[i][jj][2] + b0, d[i][jj][3] + b1);
            *(float2*)(G + (size_t)r0 * G4H + col) = v0;
            *(float2*)(G + (size_t)r1 * G4H + col) = v1;
        }
    }
}

// ---------------- C=4 chunked recurrence, UPB=16, 256 blocks @ occ 2 -----------
// 256 blocks = 2 dirs x 4 chunks x 32 blocks (same CTA/SM shape as the proven
// C=2 config). Block owns 16 hidden units = 64 rows; lane l handles rows l
// (gates 0/1) and 32+l (gates 2/3); bf16 W_hh in registers (64 u32 regs).
// Chunks: c0 t=[0,1096) true state; c1 t0=1000, c2 t0=2000, c3 t0=3000, each
// 96 burn + 1000 output steps (nS=1096 uniform). Burn h in private scratch.
__global__ __launch_bounds__(256, 2) void recur_kernel(
    const float* __restrict__ Whf, const float* __restrict__ Whb,
    const float* __restrict__ cini)
{
    const int tid = threadIdx.x;
    const int bid = blockIdx.x;
    const int dir   = bid >> 7;
    const int rem   = bid & 127;
    const int chunk = rem >> 5;
    const int blk   = rem & 31;

    const float* Wh = dir ? Whb : Whf;
    const float* G  = dir ? g_Gb : g_Gf;
    float* hs       = dir ? g_hsb : g_hsf;
    float* priv     = g_hp + (dir * 3 + (chunk > 0 ? chunk - 1 : 0)) * BUFSZ;

    const int t0 = chunk * 1000;
    const int nS = NSTEP;

    const int wid  = tid >> 5;       // warp = h segment 0..7 (64 elems)
    const int lane = tid & 31;
    const int gA = lane >> 4;        // gate of row A (0 or 1)
    const int u  = lane & 15;        // unit 0..15
    const int j0 = blk * UPB;

    // W_hh slices (bf16): rowA = gA*16+u (gates 0/1), rowB = 32+lane (gates 2/3)
    __nv_bfloat162 wA[32], wB[32];
    {
        const float* wrA = Wh + (size_t)(gA * H_DIM + j0 + u) * H_DIM + 64 * wid;
        const float* wrB = Wh + (size_t)((2 + gA) * H_DIM + j0 + u) * H_DIM + 64 * wid;
#pragma unroll
        for (int q = 0; q < 16; q++) {
            float4 v = ((const float4*)wrA)[q];
            wA[2 * q]     = __floats2bfloat162_rn(v.x, v.y);
            wA[2 * q + 1] = __floats2bfloat162_rn(v.z, v.w);
            float4 w4 = ((const float4*)wrB)[q];
            wB[2 * q]     = __floats2bfloat162_rn(w4.x, w4.y);
            wB[2 * q + 1] = __floats2bfloat162_rn(w4.z, w4.w);
        }
    }

    // cell state: warp0 lanes 0..15; chunks>0 start from zero state
    float c = 0.f;
    if (wid == 0 && lane < UPB && chunk == 0) c = cini[dir * H_DIM + j0 + lane];

    __shared__ __align__(16) float shSeg[8][64];
    __shared__ float shP[2][8][68];        // [buf][seg][row 0..63], pad 68

    const int goffA = gA * H_DIM + j0 + u;         // gates 0/1
    const int goffB = (2 + gA) * H_DIM + j0 + u;   // gates 2/3
    float gvA = 0.f, gvB = 0.f;

    for (int s = 0; s < nS; s++) {
        const int t = t0 + s;

        // ---- warp0: prefetch G[t] for both rows ----
        float gnA = 0.f, gnB = 0.f;
        if (wid == 0) {
            gnA = __ldg(G + (size_t)t * G4H + goffA);
            gnB = __ldg(G + (size_t)t * G4H + goffB);
        }

        // ---- warp0: tail of step s-1 -> h at time t ----
        if (wid == 0 && s > 0) {
            const int buf = (s + 1) & 1;
            float sumA = 0.f, sumB = 0.f;
#pragma unroll
            for (int q = 0; q < 8; q++) {
                sumA += shP[buf][q][lane];
                sumB += shP[buf][q][32 + lane];
            }
            float vA = gvA + sumA;                  // gates 0/1: sigmoid
            float actA = 0.5f * __tanhf(0.5f * vA) + 0.5f;
            float vB = gvB + sumB;                  // gate2: tanh, gate3: sigmoid
            float xin = (lane < 16) ? vB : (0.5f * vB);
            float th  = __tanhf(xin);
            float actB = (lane < 16) ? th : (0.5f * th + 0.5f);
            float ff = __shfl_sync(0xffffffffu, actA, 16 + u);
            float oo = __shfl_sync(0xffffffffu, actB, 16 + u);
            if (lane < UPB) {
                c = ff * c + actA * actB;           // i * g
                float h = oo * __tanhf(c);
                float* outRow = (chunk && (s - 1) < BURN)
                              ? (priv + (size_t)s * H_DIM)
                              : (hs + (size_t)t * H_DIM);
                strg(outRow + j0 + lane, h);
            }
        }

        // ---- workers: poll own 2 elements of h at time t ----
        {
            const float* inRow = (chunk && s <= BURN)
                               ? (priv + (size_t)s * H_DIM)
                               : (hs + (size_t)t * H_DIM);
            const float* hp = inRow + 2 * tid;
            float2 hv;
            if (s == 0) {
                hv = *(const float2*)hp;
            } else {
                hv = ldrg2(hp);
                while (hv.x == SENT || hv.y == SENT) {
                    float2 p0 = ldrg2(hp);
                    float2 p1 = ldrg2(hp);
                    hv = (p0.x != SENT && p0.y != SENT) ? p0 : p1;
                }
            }
            shSeg[wid][2 * lane]     = hv.x;
            shSeg[wid][2 * lane + 1] = hv.y;
        }
        __syncwarp();

        // ---- partial dots: rows lane and 32+lane over segment wid ----
        float aA0 = 0.f, aA1 = 0.f, aA2 = 0.f, aA3 = 0.f;
        float aB0 = 0.f, aB1 = 0.f, aB2 = 0.f, aB3 = 0.f;
        const float* sp = shSeg[wid];
#pragma unroll
        for (int q = 0; q < 16; q++) {
            float4 h4 = *(const float4*)(sp + 4 * q);
            float2 a0 = __bfloat1622float2(wA[2 * q]);
            float2 a1 = __bfloat1622float2(wA[2 * q + 1]);
            float2 b0 = __bfloat1622float2(wB[2 * q]);
            float2 b1 = __bfloat1622float2(wB[2 * q + 1]);
            aA0 = fmaf(a0.x, h4.x, aA0);
            aA1 = fmaf(a0.y, h4.y, aA1);
            aA2 = fmaf(a1.x, h4.z, aA2);
            aA3 = fmaf(a1.y, h4.w, aA3);
            aB0 = fmaf(b0.x, h4.x, aB0);
            aB1 = fmaf(b0.y, h4.y, aB1);
            aB2 = fmaf(b1.x, h4.z, aB2);
            aB3 = fmaf(b1.y, h4.w, aB3);
        }
        shP[s & 1][wid][lane]      = (aA0 + aA1) + (aA2 + aA3);
        shP[s & 1][wid][32 + lane] = (aB0 + aB1) + (aB2 + aB3);

        __syncthreads();   // one barrier per step
        gvA = gnA;
        gvB = gnB;
    }

    // ---- epilogue: tail for s = nS-1 -> h at time t0+nS (always public) ----
    if (wid == 0) {
        const int buf = (nS + 1) & 1;
        float sumA = 0.f, sumB = 0.f;
#pragma unroll
        for (int q = 0; q < 8; q++) {
            sumA += shP[buf][q][lane];
            sumB += shP[buf][q][32 + lane];
        }
        float vA = gvA + sumA;
        float actA = 0.5f * __tanhf(0.5f * vA) + 0.5f;
        float vB = gvB + sumB;
        float xin = (lane < 16) ? vB : (0.5f * vB);
        float th  = __tanhf(xin);
        float actB = (lane < 16) ? th : (0.5f * th + 0.5f);
        float ff = __shfl_sync(0xffffffffu, actA, 16 + u);
        float oo = __shfl_sync(0xffffffffu, actB, 16 + u);
        if (lane < UPB) {
            c = ff * c + actA * actB;
            float h = oo * __tanhf(c);
            strg(hs + (size_t)(t0 + nS) * H_DIM + j0 + lane, h);
        }
    }
}

// ---------------- output projection: feats[t][tag] ---------------------------
__global__ void feats_kernel(const float* __restrict__ Wout,
                             const float* __restrict__ bout)
{
    const int t = blockIdx.x;
    const int w = threadIdx.x >> 5;
    const int lane = threadIdx.x & 31;
    const float* hf = g_hsf + (size_t)(t + 1) * H_DIM;
    const float* hb = g_hsb + (size_t)(T_LEN - t) * H_DIM;
    const float* wr = Wout + w * (2 * H_DIM);

    float sum = 0.f;
#pragma unroll 4
    for (int e = lane; e < H_DIM; e += 32) sum = fmaf(hf[e], wr[e], sum);
#pragma unroll 4
    for (int e = lane; e < H_DIM; e += 32) sum = fmaf(hb[e], wr[H_DIM + e], sum);

    sum += __shfl_xor_sync(0xffffffffu, sum, 16);
    sum += __shfl_xor_sync(0xffffffffu, sum, 8);
    sum += __shfl_xor_sync(0xffffffffu, sum, 4);
    sum += __shfl_xor_sync(0xffffffffu, sum, 2);
    sum += __shfl_xor_sync(0xffffffffu, sum, 1);
    if (lane == 0) g_feats[t * TAGS + w] = sum + bout[w];
}

// ---------------- Viterbi decode + backtrack (single block, frozen) -----------
__global__ void viterbi_kernel(const float* __restrict__ trans,
                               float* __restrict__ out, int out_size)
{
    extern __shared__ float sFeats[];
    __shared__ unsigned char sBp[T_LEN * TAGS];

    const int tid = threadIdx.x;
    for (int i = tid; i < T_LEN * TAGS; i += blockDim.x) sFeats[i] = g_feats[i];
    __syncthreads();

    if (tid < 32) {
        const int lane = tid;
        float tr[TAGS];
#pragma unroll
        for (int p = 0; p < TAGS; p++) tr[p] = 0.f;
        if (lane < TAGS)
#pragma unroll
            for (int p = 0; p < TAGS; p++) tr[p] = trans[lane * TAGS + p];

        float fv = (lane == START_TAG) ? 0.f : -10000.0f;
        if (lane >= TAGS) fv = -1e30f;

        for (int t = 0; t < T_LEN; t += 2) {
#pragma unroll
            for (int uu = 0; uu < 2; uu++) {
                int tt = t + uu;
                float f0 = __shfl_sync(0xffffffffu, fv, 0);
                float f1 = __shfl_sync(0xffffffffu, fv, 1);
                float f2 = __shfl_sync(0xffffffffu, fv, 2);
                float f3 = __shfl_sync(0xffffffffu, fv, 3);
                float f4 = __shfl_sync(0xffffffffu, fv, 4);
                float s0 = f0 + tr[0], s1 = f1 + tr[1], s2 = f2 + tr[2];
                float s3 = f3 + tr[3], s4 = f4 + tr[4];
                float m01 = fmaxf(s0, s1); int b01 = (s1 > s0) ? 1 : 0;
                float m23 = fmaxf(s2, s3); int b23 = (s3 > s2) ? 3 : 2;
                float m03 = fmaxf(m01, m23); int b03 = (m23 > m01) ? b23 : b01;
                float best = fmaxf(m03, s4); int bp = (s4 > m03) ? 4 : b03;
                if (lane < TAGS) {
                    fv = best + sFeats[tt * TAGS + lane];
                    sBp[tt * TAGS + lane] = (unsigned char)bp;
                }
            }
        }

        float term = (lane < TAGS) ? (fv + trans[STOP_TAG * TAGS + lane]) : -1e30f;
        float t0 = __shfl_sync(0xffffffffu, term, 0);
        float t1 = __shfl_sync(0xffffffffu, term, 1);
        float t2 = __shfl_sync(0xffffffffu, term, 2);
        float t3 = __shfl_sync(0xffffffffu, term, 3);
        float t4 = __shfl_sync(0xffffffffu, term, 4);

        if (lane == 0) {
            float best = t0; int bl = 0;
            if (t1 > best) { best = t1; bl = 1; }
            if (t2 > best) { best = t2; bl = 2; }
            if (t3 > best) { best = t3; bl = 3; }
            if (t4 > best) { best = t4; bl = 4; }

            int base = (out_size > T_LEN) ? 1 : 0;
            if (base == 1 && out_size >= 1) out[0] = best;

            int y = bl;
            int idx = base + (T_LEN - 1);
            if (idx < out_size) out[idx] = (float)y;
            for (int t = T_LEN - 1; t >= 1; t--) {
                y = sBp[t * TAGS + y];
                idx = base + (t - 1);
                if (idx < out_size) out[idx] = (float)y;
            }
        }
    }
}

// ---------------- launcher ---------------------------------------------------
extern "C" void kernel_launch(void* const* d_in, const int* in_sizes, int n_in,
                              void* d_out, int out_size)
{
    const int*   sentence = (const int*)  d_in[0];
    const float* embed    = (const float*)d_in[1];
    const float* W_ih_f   = (const float*)d_in[2];
    const float* W_hh_f   = (const float*)d_in[3];
    const float* b_f      = (const float*)d_in[4];
    const float* W_ih_b   = (const float*)d_in[5];
    const float* W_hh_b   = (const float*)d_in[6];
    const float* b_b      = (const float*)d_in[7];
    const float* h0       = (const float*)d_in[8];
    const float* c0       = (const float*)d_in[9];
    const float* W_out    = (const float*)d_in[10];
    const float* b_out    = (const float*)d_in[11];
    const float* trans    = (const float*)d_in[12];
    float* out = (float*)d_out;

    setup_kernel<<<2048, 256>>>(h0);

    gemm_bf16<<<dim3(16, 32, 2), 256>>>(sentence, embed,
                                        W_ih_f, b_f, W_ih_b, b_b);

    recur_kernel<<<256, 256>>>(W_hh_f, W_hh_b, c0);   // 2 dirs x 4 chunks x 32

    feats_kernel<<<T_LEN, TAGS * 32>>>(W_out, b_out);

    cudaFuncSetAttribute(viterbi_kernel,
                         cudaFuncAttributeMaxDynamicSharedMemorySize,
                         T_LEN * TAGS * sizeof(float));
    viterbi_kernel<<<1, 1024, T_LEN * TAGS * sizeof(float)>>>(trans, out, out_size);
}

// round 14
// speedup vs baseline: 1.8148x; 1.8148x over previous
#include <cuda_runtime.h>
#include <cuda_bf16.h>
#include <math.h>

#define T_LEN 4096
#define E_DIM 1024
#define H_DIM 512
#define G4H   2048     // 4*H
#define UPB   8        // hidden units per recurrence block
#define TAGS  5
#define START_TAG 3
#define STOP_TAG  4
#define SENT  2.0f     // impossible h value (|h| < 1 strictly)
#define BURN  96       // burn-in steps (contraction ~0.55^96 ~ 1e-25, < fp32 ulp)
#define L_CHK (T_LEN / 2)   // 2048

// ---------------- scratch (device globals; no runtime allocation) -------------
__device__ float g_Gf[(size_t)T_LEN * G4H];          // gates fwd
__device__ float g_Gb[(size_t)T_LEN * G4H];          // gates bwd-scan
__device__ float g_hsf[(size_t)(T_LEN + 1) * H_DIM]; // h traj fwd (row0 = h0)
__device__ float g_hsb[(size_t)(T_LEN + 1) * H_DIM]; // h traj bwd-scan
__device__ float g_hpf[(BURN + 1) * H_DIM];          // chunk-1 burn-in scratch, fwd
__device__ float g_hpb[(BURN + 1) * H_DIM];          // chunk-1 burn-in scratch, bwd
__device__ float g_feats[T_LEN * TAGS];

// ---------------- helpers -----------------------------------------------------
__device__ __forceinline__ float2 ldrg2(const float* p) {
    unsigned long long u;
    asm volatile("ld.relaxed.gpu.global.b64 %0, [%1];" : "=l"(u) : "l"(p));
    float2 v;
    v.x = __uint_as_float((unsigned)(u & 0xFFFFFFFFull));
    v.y = __uint_as_float((unsigned)(u >> 32));
    return v;
}
__device__ __forceinline__ void strg(float* p, float v) {
    asm volatile("st.relaxed.gpu.global.f32 [%0], %1;" :: "l"(p), "f"(v) : "memory");
}
__device__ __forceinline__ unsigned sm_u32(const void* p) {
    unsigned r;
    asm("{ .reg .u64 t; cvta.to.shared.u64 t, %1; cvt.u32.u64 %0, t; }"
        : "=r"(r) : "l"(p));
    return r;
}
__device__ __forceinline__ void ldsm4(unsigned r[4], unsigned addr) {
    asm volatile("ldmatrix.sync.aligned.m8n8.x4.shared.b16 {%0,%1,%2,%3}, [%4];"
                 : "=r"(r[0]), "=r"(r[1]), "=r"(r[2]), "=r"(r[3]) : "r"(addr));
}
__device__ __forceinline__ void mma16816(float d[4], const unsigned a[4],
                                         unsigned b0, unsigned b1) {
    asm volatile(
        "mma.sync.aligned.m16n8k16.row.col.f32.bf16.bf16.f32 "
        "{%0,%1,%2,%3}, {%4,%5,%6,%7}, {%8,%9}, {%0,%1,%2,%3};"
        : "+f"(d[0]), "+f"(d[1]), "+f"(d[2]), "+f"(d[3])
        : "r"(a[0]), "r"(a[1]), "r"(a[2]), "r"(a[3]), "r"(b0), "r"(b1));
}

// ---------------- setup: sentinel-fill h trajectories + burn scratch ----------
__global__ void setup_kernel(const float* __restrict__ h0) {
    size_t i = (size_t)blockIdx.x * blockDim.x + threadIdx.x;
    const float4 s4 = make_float4(SENT, SENT, SENT, SENT);
    const float4 z4 = make_float4(0.f, 0.f, 0.f, 0.f);
    size_t nH4 = (size_t)T_LEN * H_DIM / 4;
    if (i < nH4) {
        ((float4*)(g_hsf + H_DIM))[i] = s4;
        ((float4*)(g_hsb + H_DIM))[i] = s4;
    }
    if (i < (BURN * H_DIM) / 4) {
        ((float4*)(g_hpf + H_DIM))[i] = s4;
        ((float4*)(g_hpb + H_DIM))[i] = s4;
    }
    if (i < H_DIM / 4) {
        ((float4*)g_hpf)[i] = z4;
        ((float4*)g_hpb)[i] = z4;
    }
    if (i < H_DIM) {
        g_hsf[i] = h0[i];
        g_hsb[i] = h0[H_DIM + i];
    }
}

// ---------------- gate GEMM: bf16 tensor cores (frozen, proven) ----------------
#define GPITCH 40

__global__ __launch_bounds__(256) void gemm_bf16(
    const int* __restrict__ sent, const float* __restrict__ embed,
    const float* __restrict__ Wf, const float* __restrict__ bf,
    const float* __restrict__ Wb, const float* __restrict__ bb)
{
    const int dir = blockIdx.z;
    const float* W    = dir ? Wb : Wf;
    const float* bias = dir ? bb : bf;
    float* G          = dir ? g_Gb : g_Gf;

    __shared__ __align__(16) unsigned short smA[128 * GPITCH];
    __shared__ __align__(16) unsigned short smB[128 * GPITCH];
    __shared__ int sRow[128];

    const int tid = threadIdx.x;
    const int m0 = blockIdx.y * 128;
    const int n0 = blockIdx.x * 128;

    if (tid < 128) {
        int t = m0 + tid;
        sRow[tid] = dir ? sent[T_LEN - 1 - t] : sent[t];
    }
    __syncthreads();

    const int srow = tid >> 1;
    const int sseg = tid & 1;
    const float* aSrc = embed + (size_t)sRow[srow] * E_DIM + sseg * 16;
    const float* bSrc = W + (size_t)(n0 + srow) * E_DIM + sseg * 16;
    unsigned short* aDst = &smA[srow * GPITCH + sseg * 16];
    unsigned short* bDst = &smB[srow * GPITCH + sseg * 16];

    const int warpId = tid >> 5;
    const int lane   = tid & 31;
    const int mbase  = (warpId & 3) * 32;
    const int nbase  = (warpId >> 2) * 64;
    const int quad   = lane >> 3;
    const int rl     = lane & 7;
    const unsigned smA0 = sm_u32(smA);
    const unsigned smB0 = sm_u32(smB);

    float d[2][8][4];
#pragma unroll
    for (int i = 0; i < 2; i++)
#pragma unroll
        for (int j = 0; j < 8; j++)
#pragma unroll
            for (int q = 0; q < 4; q++) d[i][j][q] = 0.f;

    for (int kt = 0; kt < E_DIM; kt += 32) {
        {
            float4 v0 = *(const float4*)(aSrc + kt);
            float4 v1 = *(const float4*)(aSrc + kt + 4);
            float4 v2 = *(const float4*)(aSrc + kt + 8);
            float4 v3 = *(const float4*)(aSrc + kt + 12);
            __nv_bfloat162 p[8];
            p[0] = __floats2bfloat162_rn(v0.x, v0.y);
            p[1] = __floats2bfloat162_rn(v0.z, v0.w);
            p[2] = __floats2bfloat162_rn(v1.x, v1.y);
            p[3] = __floats2bfloat162_rn(v1.z, v1.w);
            p[4] = __floats2bfloat162_rn(v2.x, v2.y);
            p[5] = __floats2bfloat162_rn(v2.z, v2.w);
            p[6] = __floats2bfloat162_rn(v3.x, v3.y);
            p[7] = __floats2bfloat162_rn(v3.z, v3.w);
            *(uint4*)(aDst)     = *(uint4*)&p[0];
            *(uint4*)(aDst + 8) = *(uint4*)&p[4];

            v0 = *(const float4*)(bSrc + kt);
            v1 = *(const float4*)(bSrc + kt + 4);
            v2 = *(const float4*)(bSrc + kt + 8);
            v3 = *(const float4*)(bSrc + kt + 12);
            p[0] = __floats2bfloat162_rn(v0.x, v0.y);
            p[1] = __floats2bfloat162_rn(v0.z, v0.w);
            p[2] = __floats2bfloat162_rn(v1.x, v1.y);
            p[3] = __floats2bfloat162_rn(v1.z, v1.w);
            p[4] = __floats2bfloat162_rn(v2.x, v2.y);
            p[5] = __floats2bfloat162_rn(v2.z, v2.w);
            p[6] = __floats2bfloat162_rn(v3.x, v3.y);
            p[7] = __floats2bfloat162_rn(v3.z, v3.w);
            *(uint4*)(bDst)     = *(uint4*)&p[0];
            *(uint4*)(bDst + 8) = *(uint4*)&p[4];
        }
        __syncthreads();

#pragma unroll
        for (int s = 0; s < 2; s++) {
            unsigned afr[2][4], bfr[4][4];
#pragma unroll
            for (int i = 0; i < 2; i++) {
                int row = mbase + i * 16 + rl + ((quad & 1) << 3);
                int col = s * 16 + ((quad & 2) << 2);
                ldsm4(afr[i], smA0 + 2 * (row * GPITCH + col));
            }
#pragma unroll
            for (int j = 0; j < 4; j++) {
                int row = nbase + j * 16 + rl + ((quad & 2) << 2);
                int col = s * 16 + ((quad & 1) << 3);
                ldsm4(bfr[j], smB0 + 2 * (row * GPITCH + col));
            }
#pragma unroll
            for (int i = 0; i < 2; i++)
#pragma unroll
                for (int j = 0; j < 4; j++) {
                    mma16816(d[i][2 * j],     afr[i], bfr[j][0], bfr[j][1]);
                    mma16816(d[i][2 * j + 1], afr[i], bfr[j][2], bfr[j][3]);
                }
        }
        __syncthreads();
    }

    const int gl = lane >> 2;
    const int lc = (lane & 3) * 2;
#pragma unroll
    for (int i = 0; i < 2; i++) {
        int r0 = m0 + mbase + i * 16 + gl;
        int r1 = r0 + 8;
#pragma unroll
        for (int jj = 0; jj < 8; jj++) {
            int col = n0 + nbase + jj * 8 + lc;
            float b0 = bias[col], b1 = bias[col + 1];
            float2 v0 = make_float2(d[i][jj][0] + b0, d[i][jj][1] + b1);
            float2 v1 = make_float2(d[i][jj][2] + b0, d[i][jj][3] + b1);
            *(float2*)(G + (size_t)r0 * G4H + col) = v0;
            *(float2*)(G + (size_t)r1 * G4H + col) = v1;
        }
    }
}

// ---------------- C=2 chunked recurrence (exact R10 config, BURN=96) -----------
// 256 blocks = 2 dirs x 2 chunks x 64 blocks @ occ 2, UPB=8, fp32 W in regs.
__global__ __launch_bounds__(256, 2) void recur_kernel(
    const float* __restrict__ Whf, const float* __restrict__ Whb,
    const float* __restrict__ c0)
{
    const int tid  = threadIdx.x;
    const int bid  = blockIdx.x;
    const int dir   = bid >> 7;
    const int chunk = (bid >> 6) & 1;
    const int blk   = bid & 63;

    const float* Wh = dir ? Whb : Whf;
    const float* G  = dir ? g_Gb : g_Gf;
    float* hs       = dir ? g_hsb : g_hsf;
    float* priv     = dir ? g_hpb : g_hpf;

    const int t0 = chunk ? (L_CHK - BURN) : 0;        // 1952 or 0
    const int nS = chunk ? (BURN + L_CHK) : L_CHK;    // 2144 or 2048

    const int wid  = tid >> 5;       // warp = h segment 0..7
    const int lane = tid & 31;       // lane = row (gate*8 + unit)
    const int r = lane >> 3;         // gate 0..3
    const int u = lane & 7;          // unit 0..7
    const int j0 = blk * UPB;

    float w[64];
    {
        const float* wr = Wh + (size_t)(r * H_DIM + j0 + u) * H_DIM + 64 * wid;
#pragma unroll
        for (int q = 0; q < 16; q++) {
            float4 v = ((const float4*)wr)[q];
            w[4 * q + 0] = v.x; w[4 * q + 1] = v.y;
            w[4 * q + 2] = v.z; w[4 * q + 3] = v.w;
        }
    }

    float c = 0.f;
    if (wid == 0 && lane < UPB && chunk == 0) c = c0[dir * H_DIM + j0 + lane];

    __shared__ __align__(16) float shSeg[8][64];
    __shared__ float shP[2][8][33];

    const int goff = r * H_DIM + j0 + u;
    float gv = 0.f;

    for (int s = 0; s < nS; s++) {
        const int t = t0 + s;

        float gnext = 0.f;
        if (wid == 0) gnext = __ldg(G + (size_t)t * G4H + goff);

        if (wid == 0 && s > 0) {
            const float* Pp = &shP[(s + 1) & 1][0][lane];
            float sum = 0.f;
#pragma unroll
            for (int q = 0; q < 8; q++) sum += Pp[q * 33];
            float v = gv + sum;
            float xin = (r == 2) ? v : (0.5f * v);
            float th  = __tanhf(xin);
            float act = (r == 2) ? th : (0.5f * th + 0.5f);
            float ff = __shfl_sync(0xffffffffu, act,  8 + u);
            float gg = __shfl_sync(0xffffffffu, act, 16 + u);
            float oo = __shfl_sync(0xffffffffu, act, 24 + u);
            if (lane < UPB) {
                c = ff * c + act * gg;
                float h = oo * __tanhf(c);
                float* outRow = (chunk && (s - 1) < BURN)
                              ? (priv + (size_t)s * H_DIM)
                              : (hs + (size_t)t * H_DIM);
                strg(outRow + j0 + lane, h);
            }
        }

        {
            const float* inRow = (chunk && s <= BURN)
                               ? (priv + (size_t)s * H_DIM)
                               : (hs + (size_t)t * H_DIM);
            const float* hp = inRow + 64 * wid + 2 * lane;
            float2 hv;
            if (s == 0) {
                hv = *(const float2*)hp;
            } else {
                hv = ldrg2(hp);
                while (hv.x == SENT || hv.y == SENT) {
                    float2 p0 = ldrg2(hp);
                    float2 p1 = ldrg2(hp);
                    hv = (p0.x != SENT && p0.y != SENT) ? p0 : p1;
                }
            }
            shSeg[wid][2 * lane]     = hv.x;
            shSeg[wid][2 * lane + 1] = hv.y;
        }
        __syncwarp();

        float a0 = 0.f, a1 = 0.f, a2 = 0.f, a3 = 0.f;
        const float* sp = shSeg[wid];
#pragma unroll
        for (int q = 0; q < 16; q++) {
            float4 h4 = *(const float4*)(sp + 4 * q);
            a0 = fmaf(w[4 * q + 0], h4.x, a0);
            a1 = fmaf(w[4 * q + 1], h4.y, a1);
            a2 = fmaf(w[4 * q + 2], h4.z, a2);
            a3 = fmaf(w[4 * q + 3], h4.w, a3);
        }
        shP[s & 1][wid][lane] = (a0 + a1) + (a2 + a3);

        __syncthreads();
        gv = gnext;
    }

    if (wid == 0) {
        const float* Pp = &shP[(nS + 1) & 1][0][lane];
        float sum = 0.f;
#pragma unroll
        for (int q = 0; q < 8; q++) sum += Pp[q * 33];
        float v = gv + sum;
        float xin = (r == 2) ? v : (0.5f * v);
        float th  = __tanhf(xin);
        float act = (r == 2) ? th : (0.5f * th + 0.5f);
        float ff = __shfl_sync(0xffffffffu, act,  8 + u);
        float gg = __shfl_sync(0xffffffffu, act, 16 + u);
        float oo = __shfl_sync(0xffffffffu, act, 24 + u);
        if (lane < UPB) {
            c = ff * c + act * gg;
            float h = oo * __tanhf(c);
            strg(hs + (size_t)(t0 + nS) * H_DIM + j0 + lane, h);
        }
    }
}

// ---------------- output projection: feats[t][tag] ---------------------------
__global__ void feats_kernel(const float* __restrict__ Wout,
                             const float* __restrict__ bout)
{
    const int t = blockIdx.x;
    const int w = threadIdx.x >> 5;
    const int lane = threadIdx.x & 31;
    const float* hf = g_hsf + (size_t)(t + 1) * H_DIM;
    const float* hb = g_hsb + (size_t)(T_LEN - t) * H_DIM;
    const float* wr = Wout + w * (2 * H_DIM);

    float sum = 0.f;
#pragma unroll 4
    for (int e = lane; e < H_DIM; e += 32) sum = fmaf(hf[e], wr[e], sum);
#pragma unroll 4
    for (int e = lane; e < H_DIM; e += 32) sum = fmaf(hb[e], wr[H_DIM + e], sum);

    sum += __shfl_xor_sync(0xffffffffu, sum, 16);
    sum += __shfl_xor_sync(0xffffffffu, sum, 8);
    sum += __shfl_xor_sync(0xffffffffu, sum, 4);
    sum += __shfl_xor_sync(0xffffffffu, sum, 2);
    sum += __shfl_xor_sync(0xffffffffu, sum, 1);
    if (lane == 0) g_feats[t * TAGS + w] = sum + bout[w];
}

// ---------------- Viterbi decode: shfl-free redundant-lane scan ----------------
// Every lane keeps all 5 fv values and updates them identically (FADD/FMNMX
// only — no inter-lane traffic in the loop). Lanes 0..4 additionally compute
// the argmax for THEIR tag from bit-identical sums (same FADD, same tournament
// order -> identical tie behavior as the proven version).
__global__ void viterbi_kernel(const float* __restrict__ trans,
                               float* __restrict__ out, int out_size)
{
    extern __shared__ float sFeats[];                 // 80 KB
    __shared__ unsigned char sBp[T_LEN * TAGS];       // 20 KB

    const int tid = threadIdx.x;
    for (int i = tid; i < T_LEN * TAGS; i += blockDim.x) sFeats[i] = g_feats[i];
    __syncthreads();

    if (tid < 32) {
        const int lane = tid;
        // full transition matrix in registers (all lanes identical)
        float trM[TAGS][TAGS];
#pragma unroll
        for (int n = 0; n < TAGS; n++)
#pragma unroll
            for (int p = 0; p < TAGS; p++) trM[n][p] = trans[n * TAGS + p];
        // own-tag row for argmax (lane n < 5 -> row n)
        const int myrow = (lane < TAGS) ? lane : 0;
        float trO[TAGS];
#pragma unroll
        for (int p = 0; p < TAGS; p++) trO[p] = trans[myrow * TAGS + p];

        float fv[TAGS];
#pragma unroll
        for (int p = 0; p < TAGS; p++) fv[p] = (p == START_TAG) ? 0.f : -10000.0f;

        float ft[TAGS];
#pragma unroll
        for (int n = 0; n < TAGS; n++) ft[n] = sFeats[n];   // prefetch t=0

        for (int t = 0; t < T_LEN; t++) {
            float ftN[TAGS];
            if (t + 1 < T_LEN) {
#pragma unroll
                for (int n = 0; n < TAGS; n++) ftN[n] = sFeats[(t + 1) * TAGS + n];
            } else {
#pragma unroll
                for (int n = 0; n < TAGS; n++) ftN[n] = 0.f;
            }

            // all-tags max update (no argmax -> pure FADD/FMNMX, all lanes)
            float best[TAGS];
#pragma unroll
            for (int n = 0; n < TAGS; n++) {
                float s0 = fv[0] + trM[n][0];
                float s1 = fv[1] + trM[n][1];
                float s2 = fv[2] + trM[n][2];
                float s3 = fv[3] + trM[n][3];
                float s4 = fv[4] + trM[n][4];
                float m01 = fmaxf(s0, s1);
                float m23 = fmaxf(s2, s3);
                best[n] = fmaxf(fmaxf(m01, m23), s4);
            }

            // own-tag argmax (bit-identical sums, identical tournament)
            {
                float s0 = fv[0] + trO[0];
                float s1 = fv[1] + trO[1];
                float s2 = fv[2] + trO[2];
                float s3 = fv[3] + trO[3];
                float s4 = fv[4] + trO[4];
                float m01 = fmaxf(s0, s1); int b01 = (s1 > s0) ? 1 : 0;
                float m23 = fmaxf(s2, s3); int b23 = (s3 > s2) ? 3 : 2;
                float m03 = fmaxf(m01, m23); int b03 = (m23 > m01) ? b23 : b01;
                int bp = (s4 > m03) ? 4 : b03;
                if (lane < TAGS) sBp[t * TAGS + lane] = (unsigned char)bp;
            }

#pragma unroll
            for (int n = 0; n < TAGS; n++) fv[n] = best[n] + ft[n];
#pragma unroll
            for (int n = 0; n < TAGS; n++) ft[n] = ftN[n];
        }

        if (lane == 0) {
            float term[TAGS];
#pragma unroll
            for (int p = 0; p < TAGS; p++)
                term[p] = fv[p] + trans[STOP_TAG * TAGS + p];
            float best = term[0]; int bl = 0;
            if (term[1] > best) { best = term[1]; bl = 1; }
            if (term[2] > best) { best = term[2]; bl = 2; }
            if (term[3] > best) { best = term[3]; bl = 3; }
            if (term[4] > best) { best = term[4]; bl = 4; }

            int base = (out_size > T_LEN) ? 1 : 0;
            if (base == 1 && out_size >= 1) out[0] = best;

            int y = bl;
            int idx = base + (T_LEN - 1);
            if (idx < out_size) out[idx] = (float)y;
            for (int t = T_LEN - 1; t >= 1; t--) {
                y = sBp[t * TAGS + y];
                idx = base + (t - 1);
                if (idx < out_size) out[idx] = (float)y;
            }
        }
    }
}

// ---------------- launcher ---------------------------------------------------
extern "C" void kernel_launch(void* const* d_in, const int* in_sizes, int n_in,
                              void* d_out, int out_size)
{
    const int*   sentence = (const int*)  d_in[0];
    const float* embed    = (const float*)d_in[1];
    const float* W_ih_f   = (const float*)d_in[2];
    const float* W_hh_f   = (const float*)d_in[3];
    const float* b_f      = (const float*)d_in[4];
    const float* W_ih_b   = (const float*)d_in[5];
    const float* W_hh_b   = (const float*)d_in[6];
    const float* b_b      = (const float*)d_in[7];
    const float* h0       = (const float*)d_in[8];
    const float* c0       = (const float*)d_in[9];
    const float* W_out    = (const float*)d_in[10];
    const float* b_out    = (const float*)d_in[11];
    const float* trans    = (const float*)d_in[12];
    float* out = (float*)d_out;

    setup_kernel<<<2048, 256>>>(h0);

    gemm_bf16<<<dim3(16, 32, 2), 256>>>(sentence, embed,
                                        W_ih_f, b_f, W_ih_b, b_b);

    recur_kernel<<<256, 256>>>(W_hh_f, W_hh_b, c0);   // 2 dirs x 2 chunks x 64

    feats_kernel<<<T_LEN, TAGS * 32>>>(W_out, b_out);

    cudaFuncSetAttribute(viterbi_kernel,
                         cudaFuncAttributeMaxDynamicSharedMemorySize,
                         T_LEN * TAGS * sizeof(float));
    viterbi_kernel<<<1, 1024, T_LEN * TAGS * sizeof(float)>>>(trans, out, out_size);
}

// round 15
// speedup vs baseline: 1.8856x; 1.0390x over previous
#include <cuda_runtime.h>
#include <cuda_bf16.h>
#include <math.h>

#define T_LEN 4096
#define E_DIM 1024
#define H_DIM 512
#define G4H   2048     // 4*H
#define UPB   8        // hidden units per recurrence block
#define TAGS  5
#define START_TAG 3
#define STOP_TAG  4
#define SENT  2.0f     // impossible h value (|h| < 1 strictly)
#define BURN  64       // burn-in steps (needs ~40; 0.55^64 ~ 2e-17, huge margin)
#define NS_CHK 2080    // balanced steps per chunk (c0: [0,2080); c1: 64 burn + 2016)
#define T1_OFF 2016    // chunk-1 start time (2080 - BURN)

// ---------------- scratch (device globals; no runtime allocation) -------------
__device__ float g_Gf[(size_t)T_LEN * G4H];          // gates fwd
__device__ float g_Gb[(size_t)T_LEN * G4H];          // gates bwd-scan
__device__ float g_hsf[(size_t)(T_LEN + 1) * H_DIM]; // h traj fwd (row0 = h0)
__device__ float g_hsb[(size_t)(T_LEN + 1) * H_DIM]; // h traj bwd-scan
__device__ float g_hpf[(BURN + 1) * H_DIM];          // chunk-1 burn-in scratch, fwd
__device__ float g_hpb[(BURN + 1) * H_DIM];          // chunk-1 burn-in scratch, bwd
__device__ float g_feats[T_LEN * TAGS];

// ---------------- helpers -----------------------------------------------------
__device__ __forceinline__ float2 ldrg2(const float* p) {
    unsigned long long u;
    asm volatile("ld.relaxed.gpu.global.b64 %0, [%1];" : "=l"(u) : "l"(p));
    float2 v;
    v.x = __uint_as_float((unsigned)(u & 0xFFFFFFFFull));
    v.y = __uint_as_float((unsigned)(u >> 32));
    return v;
}
__device__ __forceinline__ void strg(float* p, float v) {
    asm volatile("st.relaxed.gpu.global.f32 [%0], %1;" :: "l"(p), "f"(v) : "memory");
}
__device__ __forceinline__ unsigned sm_u32(const void* p) {
    unsigned r;
    asm("{ .reg .u64 t; cvta.to.shared.u64 t, %1; cvt.u32.u64 %0, t; }"
        : "=r"(r) : "l"(p));
    return r;
}
__device__ __forceinline__ void ldsm4(unsigned r[4], unsigned addr) {
    asm volatile("ldmatrix.sync.aligned.m8n8.x4.shared.b16 {%0,%1,%2,%3}, [%4];"
                 : "=r"(r[0]), "=r"(r[1]), "=r"(r[2]), "=r"(r[3]) : "r"(addr));
}
__device__ __forceinline__ void mma16816(float d[4], const unsigned a[4],
                                         unsigned b0, unsigned b1) {
    asm volatile(
        "mma.sync.aligned.m16n8k16.row.col.f32.bf16.bf16.f32 "
        "{%0,%1,%2,%3}, {%4,%5,%6,%7}, {%8,%9}, {%0,%1,%2,%3};"
        : "+f"(d[0]), "+f"(d[1]), "+f"(d[2]), "+f"(d[3])
        : "r"(a[0]), "r"(a[1]), "r"(a[2]), "r"(a[3]), "r"(b0), "r"(b1));
}

// ---------------- setup: sentinel-fill h trajectories + burn scratch ----------
__global__ void setup_kernel(const float* __restrict__ h0) {
    size_t i = (size_t)blockIdx.x * blockDim.x + threadIdx.x;
    const float4 s4 = make_float4(SENT, SENT, SENT, SENT);
    const float4 z4 = make_float4(0.f, 0.f, 0.f, 0.f);
    size_t nH4 = (size_t)T_LEN * H_DIM / 4;
    if (i < nH4) {
        ((float4*)(g_hsf + H_DIM))[i] = s4;
        ((float4*)(g_hsb + H_DIM))[i] = s4;
    }
    if (i < (BURN * H_DIM) / 4) {
        ((float4*)(g_hpf + H_DIM))[i] = s4;
        ((float4*)(g_hpb + H_DIM))[i] = s4;
    }
    if (i < H_DIM / 4) {
        ((float4*)g_hpf)[i] = z4;
        ((float4*)g_hpb)[i] = z4;
    }
    if (i < H_DIM) {
        g_hsf[i] = h0[i];
        g_hsb[i] = h0[H_DIM + i];
    }
}

// ---------------- gate GEMM: bf16 tensor cores (frozen, proven) ----------------
#define GPITCH 40

__global__ __launch_bounds__(256) void gemm_bf16(
    const int* __restrict__ sent, const float* __restrict__ embed,
    const float* __restrict__ Wf, const float* __restrict__ bf,
    const float* __restrict__ Wb, const float* __restrict__ bb)
{
    const int dir = blockIdx.z;
    const float* W    = dir ? Wb : Wf;
    const float* bias = dir ? bb : bf;
    float* G          = dir ? g_Gb : g_Gf;

    __shared__ __align__(16) unsigned short smA[128 * GPITCH];
    __shared__ __align__(16) unsigned short smB[128 * GPITCH];
    __shared__ int sRow[128];

    const int tid = threadIdx.x;
    const int m0 = blockIdx.y * 128;
    const int n0 = blockIdx.x * 128;

    if (tid < 128) {
        int t = m0 + tid;
        sRow[tid] = dir ? sent[T_LEN - 1 - t] : sent[t];
    }
    __syncthreads();

    const int srow = tid >> 1;
    const int sseg = tid & 1;
    const float* aSrc = embed + (size_t)sRow[srow] * E_DIM + sseg * 16;
    const float* bSrc = W + (size_t)(n0 + srow) * E_DIM + sseg * 16;
    unsigned short* aDst = &smA[srow * GPITCH + sseg * 16];
    unsigned short* bDst = &smB[srow * GPITCH + sseg * 16];

    const int warpId = tid >> 5;
    const int lane   = tid & 31;
    const int mbase  = (warpId & 3) * 32;
    const int nbase  = (warpId >> 2) * 64;
    const int quad   = lane >> 3;
    const int rl     = lane & 7;
    const unsigned smA0 = sm_u32(smA);
    const unsigned smB0 = sm_u32(smB);

    float d[2][8][4];
#pragma unroll
    for (int i = 0; i < 2; i++)
#pragma unroll
        for (int j = 0; j < 8; j++)
#pragma unroll
            for (int q = 0; q < 4; q++) d[i][j][q] = 0.f;

    for (int kt = 0; kt < E_DIM; kt += 32) {
        {
            float4 v0 = *(const float4*)(aSrc + kt);
            float4 v1 = *(const float4*)(aSrc + kt + 4);
            float4 v2 = *(const float4*)(aSrc + kt + 8);
            float4 v3 = *(const float4*)(aSrc + kt + 12);
            __nv_bfloat162 p[8];
            p[0] = __floats2bfloat162_rn(v0.x, v0.y);
            p[1] = __floats2bfloat162_rn(v0.z, v0.w);
            p[2] = __floats2bfloat162_rn(v1.x, v1.y);
            p[3] = __floats2bfloat162_rn(v1.z, v1.w);
            p[4] = __floats2bfloat162_rn(v2.x, v2.y);
            p[5] = __floats2bfloat162_rn(v2.z, v2.w);
            p[6] = __floats2bfloat162_rn(v3.x, v3.y);
            p[7] = __floats2bfloat162_rn(v3.z, v3.w);
            *(uint4*)(aDst)     = *(uint4*)&p[0];
            *(uint4*)(aDst + 8) = *(uint4*)&p[4];

            v0 = *(const float4*)(bSrc + kt);
            v1 = *(const float4*)(bSrc + kt + 4);
            v2 = *(const float4*)(bSrc + kt + 8);
            v3 = *(const float4*)(bSrc + kt + 12);
            p[0] = __floats2bfloat162_rn(v0.x, v0.y);
            p[1] = __floats2bfloat162_rn(v0.z, v0.w);
            p[2] = __floats2bfloat162_rn(v1.x, v1.y);
            p[3] = __floats2bfloat162_rn(v1.z, v1.w);
            p[4] = __floats2bfloat162_rn(v2.x, v2.y);
            p[5] = __floats2bfloat162_rn(v2.z, v2.w);
            p[6] = __floats2bfloat162_rn(v3.x, v3.y);
            p[7] = __floats2bfloat162_rn(v3.z, v3.w);
            *(uint4*)(bDst)     = *(uint4*)&p[0];
            *(uint4*)(bDst + 8) = *(uint4*)&p[4];
        }
        __syncthreads();

#pragma unroll
        for (int s = 0; s < 2; s++) {
            unsigned afr[2][4], bfr[4][4];
#pragma unroll
            for (int i = 0; i < 2; i++) {
                int row = mbase + i * 16 + rl + ((quad & 1) << 3);
                int col = s * 16 + ((quad & 2) << 2);
                ldsm4(afr[i], smA0 + 2 * (row * GPITCH + col));
            }
#pragma unroll
            for (int j = 0; j < 4; j++) {
                int row = nbase + j * 16 + rl + ((quad & 2) << 2);
                int col = s * 16 + ((quad & 1) << 3);
                ldsm4(bfr[j], smB0 + 2 * (row * GPITCH + col));
            }
#pragma unroll
            for (int i = 0; i < 2; i++)
#pragma unroll
                for (int j = 0; j < 4; j++) {
                    mma16816(d[i][2 * j],     afr[i], bfr[j][0], bfr[j][1]);
                    mma16816(d[i][2 * j + 1], afr[i], bfr[j][2], bfr[j][3]);
                }
        }
        __syncthreads();
    }

    const int gl = lane >> 2;
    const int lc = (lane & 3) * 2;
#pragma unroll
    for (int i = 0; i < 2; i++) {
        int r0 = m0 + mbase + i * 16 + gl;
        int r1 = r0 + 8;
#pragma unroll
        for (int jj = 0; jj < 8; jj++) {
            int col = n0 + nbase + jj * 8 + lc;
            float b0 = bias[col], b1 = bias[col + 1];
            float2 v0 = make_float2(d[i][jj][0] + b0, d[i][jj][1] + b1);
            float2 v1 = make_float2(d[i][jj][2] + b0, d[i][jj][3] + b1);
            *(float2*)(G + (size_t)r0 * G4H + col) = v0;
            *(float2*)(G + (size_t)r1 * G4H + col) = v1;
        }
    }
}

// ---------------- C=2 chunked recurrence (R10 config; BURN=64, balanced) -------
// 256 blocks = 2 dirs x 2 chunks x 64 blocks @ occ 2, UPB=8, fp32 W in regs.
// c0: t=[0,2080) from true state; c1: t0=2016, 64 burn (private) + [2080,4096).
__global__ __launch_bounds__(256, 2) void recur_kernel(
    const float* __restrict__ Whf, const float* __restrict__ Whb,
    const float* __restrict__ c0)
{
    const int tid  = threadIdx.x;
    const int bid  = blockIdx.x;
    const int dir   = bid >> 7;
    const int chunk = (bid >> 6) & 1;
    const int blk   = bid & 63;

    const float* Wh = dir ? Whb : Whf;
    const float* G  = dir ? g_Gb : g_Gf;
    float* hs       = dir ? g_hsb : g_hsf;
    float* priv     = dir ? g_hpb : g_hpf;

    const int t0 = chunk ? T1_OFF : 0;
    const int nS = NS_CHK;

    const int wid  = tid >> 5;       // warp = h segment 0..7
    const int lane = tid & 31;       // lane = row (gate*8 + unit)
    const int r = lane >> 3;         // gate 0..3
    const int u = lane & 7;          // unit 0..7
    const int j0 = blk * UPB;

    float w[64];
    {
        const float* wr = Wh + (size_t)(r * H_DIM + j0 + u) * H_DIM + 64 * wid;
#pragma unroll
        for (int q = 0; q < 16; q++) {
            float4 v = ((const float4*)wr)[q];
            w[4 * q + 0] = v.x; w[4 * q + 1] = v.y;
            w[4 * q + 2] = v.z; w[4 * q + 3] = v.w;
        }
    }

    float c = 0.f;
    if (wid == 0 && lane < UPB && chunk == 0) c = c0[dir * H_DIM + j0 + lane];

    __shared__ __align__(16) float shSeg[8][64];
    __shared__ float shP[2][8][33];

    const int goff = r * H_DIM + j0 + u;
    float gv = 0.f;

    for (int s = 0; s < nS; s++) {
        const int t = t0 + s;

        float gnext = 0.f;
        if (wid == 0) gnext = __ldg(G + (size_t)t * G4H + goff);

        if (wid == 0 && s > 0) {
            const float* Pp = &shP[(s + 1) & 1][0][lane];
            float sum = 0.f;
#pragma unroll
            for (int q = 0; q < 8; q++) sum += Pp[q * 33];
            float v = gv + sum;
            float xin = (r == 2) ? v : (0.5f * v);
            float th  = __tanhf(xin);
            float act = (r == 2) ? th : (0.5f * th + 0.5f);
            float ff = __shfl_sync(0xffffffffu, act,  8 + u);
            float gg = __shfl_sync(0xffffffffu, act, 16 + u);
            float oo = __shfl_sync(0xffffffffu, act, 24 + u);
            if (lane < UPB) {
                c = ff * c + act * gg;
                float h = oo * __tanhf(c);
                float* outRow = (chunk && (s - 1) < BURN)
                              ? (priv + (size_t)s * H_DIM)
                              : (hs + (size_t)t * H_DIM);
                strg(outRow + j0 + lane, h);
            }
        }

        {
            const float* inRow = (chunk && s <= BURN)
                               ? (priv + (size_t)s * H_DIM)
                               : (hs + (size_t)t * H_DIM);
            const float* hp = inRow + 64 * wid + 2 * lane;
            float2 hv;
            if (s == 0) {
                hv = *(const float2*)hp;
            } else {
                hv = ldrg2(hp);
                while (hv.x == SENT || hv.y == SENT) {
                    float2 p0 = ldrg2(hp);
                    float2 p1 = ldrg2(hp);
                    hv = (p0.x != SENT && p0.y != SENT) ? p0 : p1;
                }
            }
            shSeg[wid][2 * lane]     = hv.x;
            shSeg[wid][2 * lane + 1] = hv.y;
        }
        __syncwarp();

        float a0 = 0.f, a1 = 0.f, a2 = 0.f, a3 = 0.f;
        const float* sp = shSeg[wid];
#pragma unroll
        for (int q = 0; q < 16; q++) {
            float4 h4 = *(const float4*)(sp + 4 * q);
            a0 = fmaf(w[4 * q + 0], h4.x, a0);
            a1 = fmaf(w[4 * q + 1], h4.y, a1);
            a2 = fmaf(w[4 * q + 2], h4.z, a2);
            a3 = fmaf(w[4 * q + 3], h4.w, a3);
        }
        shP[s & 1][wid][lane] = (a0 + a1) + (a2 + a3);

        __syncthreads();
        gv = gnext;
    }

    if (wid == 0) {
        const float* Pp = &shP[(nS + 1) & 1][0][lane];
        float sum = 0.f;
#pragma unroll
        for (int q = 0; q < 8; q++) sum += Pp[q * 33];
        float v = gv + sum;
        float xin = (r == 2) ? v : (0.5f * v);
        float th  = __tanhf(xin);
        float act = (r == 2) ? th : (0.5f * th + 0.5f);
        float ff = __shfl_sync(0xffffffffu, act,  8 + u);
        float gg = __shfl_sync(0xffffffffu, act, 16 + u);
        float oo = __shfl_sync(0xffffffffu, act, 24 + u);
        if (lane < UPB) {
            c = ff * c + act * gg;
            float h = oo * __tanhf(c);
            strg(hs + (size_t)(t0 + nS) * H_DIM + j0 + lane, h);
        }
    }
}

// ---------------- output projection: feats[t][tag] ---------------------------
__global__ void feats_kernel(const float* __restrict__ Wout,
                             const float* __restrict__ bout)
{
    const int t = blockIdx.x;
    const int w = threadIdx.x >> 5;
    const int lane = threadIdx.x & 31;
    const float* hf = g_hsf + (size_t)(t + 1) * H_DIM;
    const float* hb = g_hsb + (size_t)(T_LEN - t) * H_DIM;
    const float* wr = Wout + w * (2 * H_DIM);

    float sum = 0.f;
#pragma unroll 4
    for (int e = lane; e < H_DIM; e += 32) sum = fmaf(hf[e], wr[e], sum);
#pragma unroll 4
    for (int e = lane; e < H_DIM; e += 32) sum = fmaf(hb[e], wr[H_DIM + e], sum);

    sum += __shfl_xor_sync(0xffffffffu, sum, 16);
    sum += __shfl_xor_sync(0xffffffffu, sum, 8);
    sum += __shfl_xor_sync(0xffffffffu, sum, 4);
    sum += __shfl_xor_sync(0xffffffffu, sum, 2);
    sum += __shfl_xor_sync(0xffffffffu, sum, 1);
    if (lane == 0) g_feats[t * TAGS + w] = sum + bout[w];
}

// ---------------- Viterbi decode + backtrack (R10 proven version) --------------
__global__ void viterbi_kernel(const float* __restrict__ trans,
                               float* __restrict__ out, int out_size)
{
    extern __shared__ float sFeats[];
    __shared__ unsigned char sBp[T_LEN * TAGS];

    const int tid = threadIdx.x;
    for (int i = tid; i < T_LEN * TAGS; i += blockDim.x) sFeats[i] = g_feats[i];
    __syncthreads();

    if (tid < 32) {
        const int lane = tid;
        float tr[TAGS];
#pragma unroll
        for (int p = 0; p < TAGS; p++) tr[p] = 0.f;
        if (lane < TAGS)
#pragma unroll
            for (int p = 0; p < TAGS; p++) tr[p] = trans[lane * TAGS + p];

        float fv = (lane == START_TAG) ? 0.f : -10000.0f;
        if (lane >= TAGS) fv = -1e30f;

        for (int t = 0; t < T_LEN; t += 2) {
#pragma unroll
            for (int uu = 0; uu < 2; uu++) {
                int tt = t + uu;
                float f0 = __shfl_sync(0xffffffffu, fv, 0);
                float f1 = __shfl_sync(0xffffffffu, fv, 1);
                float f2 = __shfl_sync(0xffffffffu, fv, 2);
                float f3 = __shfl_sync(0xffffffffu, fv, 3);
                float f4 = __shfl_sync(0xffffffffu, fv, 4);
                float s0 = f0 + tr[0], s1 = f1 + tr[1], s2 = f2 + tr[2];
                float s3 = f3 + tr[3], s4 = f4 + tr[4];
                float m01 = fmaxf(s0, s1); int b01 = (s1 > s0) ? 1 : 0;
                float m23 = fmaxf(s2, s3); int b23 = (s3 > s2) ? 3 : 2;
                float m03 = fmaxf(m01, m23); int b03 = (m23 > m01) ? b23 : b01;
                float best = fmaxf(m03, s4); int bp = (s4 > m03) ? 4 : b03;
                if (lane < TAGS) {
                    fv = best + sFeats[tt * TAGS + lane];
                    sBp[tt * TAGS + lane] = (unsigned char)bp;
                }
            }
        }

        float term = (lane < TAGS) ? (fv + trans[STOP_TAG * TAGS + lane]) : -1e30f;
        float t0 = __shfl_sync(0xffffffffu, term, 0);
        float t1 = __shfl_sync(0xffffffffu, term, 1);
        float t2 = __shfl_sync(0xffffffffu, term, 2);
        float t3 = __shfl_sync(0xffffffffu, term, 3);
        float t4 = __shfl_sync(0xffffffffu, term, 4);

        if (lane == 0) {
            float best = t0; int bl = 0;
            if (t1 > best) { best = t1; bl = 1; }
            if (t2 > best) { best = t2; bl = 2; }
            if (t3 > best) { best = t3; bl = 3; }
            if (t4 > best) { best = t4; bl = 4; }

            int base = (out_size > T_LEN) ? 1 : 0;
            if (base == 1 && out_size >= 1) out[0] = best;

            int y = bl;
            int idx = base + (T_LEN - 1);
            if (idx < out_size) out[idx] = (float)y;
            for (int t = T_LEN - 1; t >= 1; t--) {
                y = sBp[t * TAGS + y];
                idx = base + (t - 1);
                if (idx < out_size) out[idx] = (float)y;
            }
        }
    }
}

// ---------------- launcher ---------------------------------------------------
extern "C" void kernel_launch(void* const* d_in, const int* in_sizes, int n_in,
                              void* d_out, int out_size)
{
    const int*   sentence = (const int*)  d_in[0];
    const float* embed    = (const float*)d_in[1];
    const float* W_ih_f   = (const float*)d_in[2];
    const float* W_hh_f   = (const float*)d_in[3];
    const float* b_f      = (const float*)d_in[4];
    const float* W_ih_b   = (const float*)d_in[5];
    const float* W_hh_b   = (const float*)d_in[6];
    const float* b_b      = (const float*)d_in[7];
    const float* h0       = (const float*)d_in[8];
    const float* c0       = (const float*)d_in[9];
    const float* W_out    = (const float*)d_in[10];
    const float* b_out    = (const float*)d_in[11];
    const float* trans    = (const float*)d_in[12];
    float* out = (float*)d_out;

    setup_kernel<<<2048, 256>>>(h0);

    gemm_bf16<<<dim3(16, 32, 2), 256>>>(sentence, embed,
                                        W_ih_f, b_f, W_ih_b, b_b);

    recur_kernel<<<256, 256>>>(W_hh_f, W_hh_b, c0);   // 2 dirs x 2 chunks x 64

    feats_kernel<<<T_LEN, TAGS * 32>>>(W_out, b_out);

    cudaFuncSetAttribute(viterbi_kernel,
                         cudaFuncAttributeMaxDynamicSharedMemorySize,
                         T_LEN * TAGS * sizeof(float));
    viterbi_kernel<<<1, 1024, T_LEN * TAGS * sizeof(float)>>>(trans, out, out_size);
}

// round 16
// speedup vs baseline: 1.9440x; 1.0310x over previous
#include <cuda_runtime.h>
#include <cuda_bf16.h>
#include <math.h>

#define T_LEN 4096
#define E_DIM 1024
#define H_DIM 512
#define G4H   2048     // 4*H
#define UPB   8        // hidden units per recurrence block
#define TAGS  5
#define START_TAG 3
#define STOP_TAG  4
#define SENT  2.0f     // impossible h value (|h| < 1 strictly)
#define BURN  64       // burn-in steps (needs ~40; 0.55^64 ~ 2e-17, huge margin)
#define NS_CHK 2080    // balanced steps per chunk
#define T1_OFF 2016    // chunk-1 start time (2080 - BURN)

// ---------------- scratch (device globals; no runtime allocation) -------------
__device__ float g_Gf[(size_t)T_LEN * G4H];          // gates fwd
__device__ float g_Gb[(size_t)T_LEN * G4H];          // gates bwd-scan
__device__ float g_hsf[(size_t)(T_LEN + 1) * H_DIM]; // h traj fwd (row0 = h0)
__device__ float g_hsb[(size_t)(T_LEN + 1) * H_DIM]; // h traj bwd-scan
__device__ float g_hpf[(BURN + 1) * H_DIM];          // chunk-1 burn-in scratch, fwd
__device__ float g_hpb[(BURN + 1) * H_DIM];          // chunk-1 burn-in scratch, bwd
__device__ float g_feats[T_LEN * TAGS];
__device__ float g_dump[64];                          // branchless-store sink

// ---------------- helpers -----------------------------------------------------
__device__ __forceinline__ float2 ldrg2(const float* p) {
    unsigned long long u;
    asm volatile("ld.relaxed.gpu.global.b64 %0, [%1];" : "=l"(u) : "l"(p));
    float2 v;
    v.x = __uint_as_float((unsigned)(u & 0xFFFFFFFFull));
    v.y = __uint_as_float((unsigned)(u >> 32));
    return v;
}
__device__ __forceinline__ void strg(float* p, float v) {
    asm volatile("st.relaxed.gpu.global.f32 [%0], %1;" :: "l"(p), "f"(v) : "memory");
}
__device__ __forceinline__ unsigned sm_u32(const void* p) {
    unsigned r;
    asm("{ .reg .u64 t; cvta.to.shared.u64 t, %1; cvt.u32.u64 %0, t; }"
        : "=r"(r) : "l"(p));
    return r;
}
__device__ __forceinline__ void ldsm4(unsigned r[4], unsigned addr) {
    asm volatile("ldmatrix.sync.aligned.m8n8.x4.shared.b16 {%0,%1,%2,%3}, [%4];"
                 : "=r"(r[0]), "=r"(r[1]), "=r"(r[2]), "=r"(r[3]) : "r"(addr));
}
__device__ __forceinline__ void mma16816(float d[4], const unsigned a[4],
                                         unsigned b0, unsigned b1) {
    asm volatile(
        "mma.sync.aligned.m16n8k16.row.col.f32.bf16.bf16.f32 "
        "{%0,%1,%2,%3}, {%4,%5,%6,%7}, {%8,%9}, {%0,%1,%2,%3};"
        : "+f"(d[0]), "+f"(d[1]), "+f"(d[2]), "+f"(d[3])
        : "r"(a[0]), "r"(a[1]), "r"(a[2]), "r"(a[3]), "r"(b0), "r"(b1));
}

// ---------------- setup: sentinel-fill h trajectories + burn scratch ----------
__global__ void setup_kernel(const float* __restrict__ h0) {
    size_t i = (size_t)blockIdx.x * blockDim.x + threadIdx.x;
    const float4 s4 = make_float4(SENT, SENT, SENT, SENT);
    const float4 z4 = make_float4(0.f, 0.f, 0.f, 0.f);
    size_t nH4 = (size_t)T_LEN * H_DIM / 4;
    if (i < nH4) {
        ((float4*)(g_hsf + H_DIM))[i] = s4;
        ((float4*)(g_hsb + H_DIM))[i] = s4;
    }
    if (i < (BURN * H_DIM) / 4) {
        ((float4*)(g_hpf + H_DIM))[i] = s4;
        ((float4*)(g_hpb + H_DIM))[i] = s4;
    }
    if (i < H_DIM / 4) {
        ((float4*)g_hpf)[i] = z4;
        ((float4*)g_hpb)[i] = z4;
    }
    if (i < H_DIM) {
        g_hsf[i] = h0[i];
        g_hsb[i] = h0[H_DIM + i];
    }
}

// ---------------- gate GEMM: bf16 tensor cores (frozen, proven) ----------------
#define GPITCH 40

__global__ __launch_bounds__(256) void gemm_bf16(
    const int* __restrict__ sent, const float* __restrict__ embed,
    const float* __restrict__ Wf, const float* __restrict__ bf,
    const float* __restrict__ Wb, const float* __restrict__ bb)
{
    const int dir = blockIdx.z;
    const float* W    = dir ? Wb : Wf;
    const float* bias = dir ? bb : bf;
    float* G          = dir ? g_Gb : g_Gf;

    __shared__ __align__(16) unsigned short smA[128 * GPITCH];
    __shared__ __align__(16) unsigned short smB[128 * GPITCH];
    __shared__ int sRow[128];

    const int tid = threadIdx.x;
    const int m0 = blockIdx.y * 128;
    const int n0 = blockIdx.x * 128;

    if (tid < 128) {
        int t = m0 + tid;
        sRow[tid] = dir ? sent[T_LEN - 1 - t] : sent[t];
    }
    __syncthreads();

    const int srow = tid >> 1;
    const int sseg = tid & 1;
    const float* aSrc = embed + (size_t)sRow[srow] * E_DIM + sseg * 16;
    const float* bSrc = W + (size_t)(n0 + srow) * E_DIM + sseg * 16;
    unsigned short* aDst = &smA[srow * GPITCH + sseg * 16];
    unsigned short* bDst = &smB[srow * GPITCH + sseg * 16];

    const int warpId = tid >> 5;
    const int lane   = tid & 31;
    const int mbase  = (warpId & 3) * 32;
    const int nbase  = (warpId >> 2) * 64;
    const int quad   = lane >> 3;
    const int rl     = lane & 7;
    const unsigned smA0 = sm_u32(smA);
    const unsigned smB0 = sm_u32(smB);

    float d[2][8][4];
#pragma unroll
    for (int i = 0; i < 2; i++)
#pragma unroll
        for (int j = 0; j < 8; j++)
#pragma unroll
            for (int q = 0; q < 4; q++) d[i][j][q] = 0.f;

    for (int kt = 0; kt < E_DIM; kt += 32) {
        {
            float4 v0 = *(const float4*)(aSrc + kt);
            float4 v1 = *(const float4*)(aSrc + kt + 4);
            float4 v2 = *(const float4*)(aSrc + kt + 8);
            float4 v3 = *(const float4*)(aSrc + kt + 12);
            __nv_bfloat162 p[8];
            p[0] = __floats2bfloat162_rn(v0.x, v0.y);
            p[1] = __floats2bfloat162_rn(v0.z, v0.w);
            p[2] = __floats2bfloat162_rn(v1.x, v1.y);
            p[3] = __floats2bfloat162_rn(v1.z, v1.w);
            p[4] = __floats2bfloat162_rn(v2.x, v2.y);
            p[5] = __floats2bfloat162_rn(v2.z, v2.w);
            p[6] = __floats2bfloat162_rn(v3.x, v3.y);
            p[7] = __floats2bfloat162_rn(v3.z, v3.w);
            *(uint4*)(aDst)     = *(uint4*)&p[0];
            *(uint4*)(aDst + 8) = *(uint4*)&p[4];

            v0 = *(const float4*)(bSrc + kt);
            v1 = *(const float4*)(bSrc + kt + 4);
            v2 = *(const float4*)(bSrc + kt + 8);
            v3 = *(const float4*)(bSrc + kt + 12);
            p[0] = __floats2bfloat162_rn(v0.x, v0.y);
            p[1] = __floats2bfloat162_rn(v0.z, v0.w);
            p[2] = __floats2bfloat162_rn(v1.x, v1.y);
            p[3] = __floats2bfloat162_rn(v1.z, v1.w);
            p[4] = __floats2bfloat162_rn(v2.x, v2.y);
            p[5] = __floats2bfloat162_rn(v2.z, v2.w);
            p[6] = __floats2bfloat162_rn(v3.x, v3.y);
            p[7] = __floats2bfloat162_rn(v3.z, v3.w);
            *(uint4*)(bDst)     = *(uint4*)&p[0];
            *(uint4*)(bDst + 8) = *(uint4*)&p[4];
        }
        __syncthreads();

#pragma unroll
        for (int s = 0; s < 2; s++) {
            unsigned afr[2][4], bfr[4][4];
#pragma unroll
            for (int i = 0; i < 2; i++) {
                int row = mbase + i * 16 + rl + ((quad & 1) << 3);
                int col = s * 16 + ((quad & 2) << 2);
                ldsm4(afr[i], smA0 + 2 * (row * GPITCH + col));
            }
#pragma unroll
            for (int j = 0; j < 4; j++) {
                int row = nbase + j * 16 + rl + ((quad & 2) << 2);
                int col = s * 16 + ((quad & 1) << 3);
                ldsm4(bfr[j], smB0 + 2 * (row * GPITCH + col));
            }
#pragma unroll
            for (int i = 0; i < 2; i++)
#pragma unroll
                for (int j = 0; j < 4; j++) {
                    mma16816(d[i][2 * j],     afr[i], bfr[j][0], bfr[j][1]);
                    mma16816(d[i][2 * j + 1], afr[i], bfr[j][2], bfr[j][3]);
                }
        }
        __syncthreads();
    }

    const int gl = lane >> 2;
    const int lc = (lane & 3) * 2;
#pragma unroll
    for (int i = 0; i < 2; i++) {
        int r0 = m0 + mbase + i * 16 + gl;
        int r1 = r0 + 8;
#pragma unroll
        for (int jj = 0; jj < 8; jj++) {
            int col = n0 + nbase + jj * 8 + lc;
            float b0 = bias[col], b1 = bias[col + 1];
            float2 v0 = make_float2(d[i][jj][0] + b0, d[i][jj][1] + b1);
            float2 v1 = make_float2(d[i][jj][2] + b0, d[i][jj][3] + b1);
            *(float2*)(G + (size_t)r0 * G4H + col) = v0;
            *(float2*)(G + (size_t)r1 * G4H + col) = v1;
        }
    }
}

// ---------------- C=2 chunked recurrence (BURN=64; branchless tail store) ------
__global__ __launch_bounds__(256, 2) void recur_kernel(
    const float* __restrict__ Whf, const float* __restrict__ Whb,
    const float* __restrict__ c0)
{
    const int tid  = threadIdx.x;
    const int bid  = blockIdx.x;
    const int dir   = bid >> 7;
    const int chunk = (bid >> 6) & 1;
    const int blk   = bid & 63;

    const float* Wh = dir ? Whb : Whf;
    const float* G  = dir ? g_Gb : g_Gf;
    float* hs       = dir ? g_hsb : g_hsf;
    float* priv     = dir ? g_hpb : g_hpf;

    const int t0 = chunk ? T1_OFF : 0;
    const int nS = NS_CHK;

    const int wid  = tid >> 5;       // warp = h segment 0..7
    const int lane = tid & 31;       // lane = row (gate*8 + unit)
    const int r = lane >> 3;         // gate 0..3
    const int u = lane & 7;          // unit 0..7
    const int j0 = blk * UPB;

    float w[64];
    {
        const float* wr = Wh + (size_t)(r * H_DIM + j0 + u) * H_DIM + 64 * wid;
#pragma unroll
        for (int q = 0; q < 16; q++) {
            float4 v = ((const float4*)wr)[q];
            w[4 * q + 0] = v.x; w[4 * q + 1] = v.y;
            w[4 * q + 2] = v.z; w[4 * q + 3] = v.w;
        }
    }

    float c = 0.f;
    if (wid == 0 && lane < UPB && chunk == 0) c = c0[dir * H_DIM + j0 + lane];

    __shared__ __align__(16) float shSeg[8][64];
    __shared__ float shP[2][8][33];

    const int goff = r * H_DIM + j0 + u;
    float gv = 0.f;

    for (int s = 0; s < nS; s++) {
        const int t = t0 + s;

        float gnext = 0.f;
        if (wid == 0) gnext = __ldg(G + (size_t)t * G4H + goff);

        if (wid == 0 && s > 0) {
            const float* Pp = &shP[(s + 1) & 1][0][lane];
            float sum = 0.f;
#pragma unroll
            for (int q = 0; q < 8; q++) sum += Pp[q * 33];
            float v = gv + sum;
            float xin = (r == 2) ? v : (0.5f * v);
            float th  = __tanhf(xin);
            float act = (r == 2) ? th : (0.5f * th + 0.5f);
            float ff = __shfl_sync(0xffffffffu, act,  8 + u);
            float gg = __shfl_sync(0xffffffffu, act, 16 + u);
            float oo = __shfl_sync(0xffffffffu, act, 24 + u);
            // branchless: all 32 lanes compute (finite garbage for lane>=8),
            // address-select sinks lanes>=8 into g_dump (no BSSY on hot path)
            c = ff * c + act * gg;
            float h = oo * __tanhf(c);
            float* outRow = (chunk && (s - 1) < BURN)
                          ? (priv + (size_t)s * H_DIM)
                          : (hs + (size_t)t * H_DIM);
            float* dst = (lane < UPB) ? (outRow + j0 + lane) : (g_dump + lane);
            strg(dst, h);
        }

        {
            const float* inRow = (chunk && s <= BURN)
                               ? (priv + (size_t)s * H_DIM)
                               : (hs + (size_t)t * H_DIM);
            const float* hp = inRow + 64 * wid + 2 * lane;
            float2 hv;
            if (s == 0) {
                hv = *(const float2*)hp;
            } else {
                hv = ldrg2(hp);
                while (hv.x == SENT || hv.y == SENT) {
                    float2 p0 = ldrg2(hp);
                    float2 p1 = ldrg2(hp);
                    hv = (p0.x != SENT && p0.y != SENT) ? p0 : p1;
                }
            }
            shSeg[wid][2 * lane]     = hv.x;
            shSeg[wid][2 * lane + 1] = hv.y;
        }
        __syncwarp();

        float a0 = 0.f, a1 = 0.f, a2 = 0.f, a3 = 0.f;
        const float* sp = shSeg[wid];
#pragma unroll
        for (int q = 0; q < 16; q++) {
            float4 h4 = *(const float4*)(sp + 4 * q);
            a0 = fmaf(w[4 * q + 0], h4.x, a0);
            a1 = fmaf(w[4 * q + 1], h4.y, a1);
            a2 = fmaf(w[4 * q + 2], h4.z, a2);
            a3 = fmaf(w[4 * q + 3], h4.w, a3);
        }
        shP[s & 1][wid][lane] = (a0 + a1) + (a2 + a3);

        __syncthreads();
        gv = gnext;
    }

    if (wid == 0) {
        const float* Pp = &shP[(nS + 1) & 1][0][lane];
        float sum = 0.f;
#pragma unroll
        for (int q = 0; q < 8; q++) sum += Pp[q * 33];
        float v = gv + sum;
        float xin = (r == 2) ? v : (0.5f * v);
        float th  = __tanhf(xin);
        float act = (r == 2) ? th : (0.5f * th + 0.5f);
        float ff = __shfl_sync(0xffffffffu, act,  8 + u);
        float gg = __shfl_sync(0xffffffffu, act, 16 + u);
        float oo = __shfl_sync(0xffffffffu, act, 24 + u);
        if (lane < UPB) {
            c = ff * c + act * gg;
            float h = oo * __tanhf(c);
            strg(hs + (size_t)(t0 + nS) * H_DIM + j0 + lane, h);
        }
    }
}

// ---------------- output projection: feats[t][tag] ---------------------------
__global__ void feats_kernel(const float* __restrict__ Wout,
                             const float* __restrict__ bout)
{
    const int t = blockIdx.x;
    const int w = threadIdx.x >> 5;
    const int lane = threadIdx.x & 31;
    const float* hf = g_hsf + (size_t)(t + 1) * H_DIM;
    const float* hb = g_hsb + (size_t)(T_LEN - t) * H_DIM;
    const float* wr = Wout + w * (2 * H_DIM);

    float sum = 0.f;
#pragma unroll 4
    for (int e = lane; e < H_DIM; e += 32) sum = fmaf(hf[e], wr[e], sum);
#pragma unroll 4
    for (int e = lane; e < H_DIM; e += 32) sum = fmaf(hb[e], wr[H_DIM + e], sum);

    sum += __shfl_xor_sync(0xffffffffu, sum, 16);
    sum += __shfl_xor_sync(0xffffffffu, sum, 8);
    sum += __shfl_xor_sync(0xffffffffu, sum, 4);
    sum += __shfl_xor_sync(0xffffffffu, sum, 2);
    sum += __shfl_xor_sync(0xffffffffu, sum, 1);
    if (lane == 0) g_feats[t * TAGS + w] = sum + bout[w];
}

// ---------------- Viterbi decode: branchless inner loop ------------------------
// Same arithmetic/op-order as the proven R10 version; the per-iter divergent
// if (lane<TAGS){...} is replaced by predicated SEL + address-select store
// (ptxas emits BSSY/BSYNC for short if-arms: ~70 cyc/iter removed).
__global__ void viterbi_kernel(const float* __restrict__ trans,
                               float* __restrict__ out, int out_size)
{
    extern __shared__ float sFeats[];                 // 80 KB
    __shared__ unsigned char sBp[T_LEN * TAGS];       // 20 KB
    __shared__ unsigned char sDump[32];               // branchless-store sink

    const int tid = threadIdx.x;
    for (int i = tid; i < T_LEN * TAGS; i += blockDim.x) sFeats[i] = g_feats[i];
    __syncthreads();

    if (tid < 32) {
        const int lane = tid;
        const bool valid = (lane < TAGS);
        float tr[TAGS];
#pragma unroll
        for (int p = 0; p < TAGS; p++) tr[p] = 0.f;
        if (valid)
#pragma unroll
            for (int p = 0; p < TAGS; p++) tr[p] = trans[lane * TAGS + p];

        float fv = (lane == START_TAG) ? 0.f : -10000.0f;
        if (!valid) fv = -1e30f;

        const int featLane = valid ? lane : 0;        // always-valid smem index

        for (int t = 0; t < T_LEN; t += 2) {
#pragma unroll
            for (int uu = 0; uu < 2; uu++) {
                int tt = t + uu;
                float f0 = __shfl_sync(0xffffffffu, fv, 0);
                float f1 = __shfl_sync(0xffffffffu, fv, 1);
                float f2 = __shfl_sync(0xffffffffu, fv, 2);
                float f3 = __shfl_sync(0xffffffffu, fv, 3);
                float f4 = __shfl_sync(0xffffffffu, fv, 4);
                float s0 = f0 + tr[0], s1 = f1 + tr[1], s2 = f2 + tr[2];
                float s3 = f3 + tr[3], s4 = f4 + tr[4];
                float m01 = fmaxf(s0, s1); int b01 = (s1 > s0) ? 1 : 0;
                float m23 = fmaxf(s2, s3); int b23 = (s3 > s2) ? 3 : 2;
                float m03 = fmaxf(m01, m23); int b03 = (m23 > m01) ? b23 : b01;
                float best = fmaxf(m03, s4); int bp = (s4 > m03) ? 4 : b03;
                float feat = sFeats[tt * TAGS + featLane];
                fv = valid ? (best + feat) : fv;                      // SEL, no BSSY
                unsigned char* bpPtr = valid ? &sBp[tt * TAGS + lane]
                                             : &sDump[lane];          // addr select
                *bpPtr = (unsigned char)bp;                           // uncond STS.U8
            }
        }

        float term = valid ? (fv + trans[STOP_TAG * TAGS + lane]) : -1e30f;
        float t0 = __shfl_sync(0xffffffffu, term, 0);
        float t1 = __shfl_sync(0xffffffffu, term, 1);
        float t2 = __shfl_sync(0xffffffffu, term, 2);
        float t3 = __shfl_sync(0xffffffffu, term, 3);
        float t4 = __shfl_sync(0xffffffffu, term, 4);

        if (lane == 0) {
            float best = t0; int bl = 0;
            if (t1 > best) { best = t1; bl = 1; }
            if (t2 > best) { best = t2; bl = 2; }
            if (t3 > best) { best = t3; bl = 3; }
            if (t4 > best) { best = t4; bl = 4; }

            int base = (out_size > T_LEN) ? 1 : 0;
            if (base == 1 && out_size >= 1) out[0] = best;

            int y = bl;
            int idx = base + (T_LEN - 1);
            if (idx < out_size) out[idx] = (float)y;
            for (int t = T_LEN - 1; t >= 1; t--) {
                y = sBp[t * TAGS + y];
                idx = base + (t - 1);
                if (idx < out_size) out[idx] = (float)y;
            }
        }
    }
}

// ---------------- launcher ---------------------------------------------------
extern "C" void kernel_launch(void* const* d_in, const int* in_sizes, int n_in,
                              void* d_out, int out_size)
{
    const int*   sentence = (const int*)  d_in[0];
    const float* embed    = (const float*)d_in[1];
    const float* W_ih_f   = (const float*)d_in[2];
    const float* W_hh_f   = (const float*)d_in[3];
    const float* b_f      = (const float*)d_in[4];
    const float* W_ih_b   = (const float*)d_in[5];
    const float* W_hh_b   = (const float*)d_in[6];
    const float* b_b      = (const float*)d_in[7];
    const float* h0       = (const float*)d_in[8];
    const float* c0       = (const float*)d_in[9];
    const float* W_out    = (const float*)d_in[10];
    const float* b_out    = (const float*)d_in[11];
    const float* trans    = (const float*)d_in[12];
    float* out = (float*)d_out;

    setup_kernel<<<2048, 256>>>(h0);

    gemm_bf16<<<dim3(16, 32, 2), 256>>>(sentence, embed,
                                        W_ih_f, b_f, W_ih_b, b_b);

    recur_kernel<<<256, 256>>>(W_hh_f, W_hh_b, c0);   // 2 dirs x 2 chunks x 64

    feats_kernel<<<T_LEN, TAGS * 32>>>(W_out, b_out);

    cudaFuncSetAttribute(viterbi_kernel,
                         cudaFuncAttributeMaxDynamicSharedMemorySize,
                         T_LEN * TAGS * sizeof(float));
    viterbi_kernel<<<1, 1024, T_LEN * TAGS * sizeof(float)>>>(trans, out, out_size);
}

// round 17
// speedup vs baseline: 1.9488x; 1.0024x over previous
#include <cuda_runtime.h>
#include <cuda_bf16.h>
#include <math.h>

#define T_LEN 4096
#define E_DIM 1024
#define H_DIM 512
#define G4H   2048     // 4*H
#define UPB   8        // hidden units per recurrence block
#define TAGS  5
#define START_TAG 3
#define STOP_TAG  4
#define SENT  2.0f     // impossible h value (|h| < 1 strictly)
#define BURN  64       // burn-in steps (needs ~40; 0.55^64 ~ 2e-17, huge margin)
#define NS_CHK 2080    // balanced steps per chunk
#define T1_OFF 2016    // chunk-1 start time (2080 - BURN)

// ---------------- scratch (device globals; no runtime allocation) -------------
__device__ float g_Gf[(size_t)T_LEN * G4H];          // gates fwd
__device__ float g_Gb[(size_t)T_LEN * G4H];          // gates bwd-scan
__device__ float g_hsf[(size_t)(T_LEN + 1) * H_DIM]; // h traj fwd (row0 = h0)
__device__ float g_hsb[(size_t)(T_LEN + 1) * H_DIM]; // h traj bwd-scan
__device__ float g_hpf[(BURN + 1) * H_DIM];          // chunk-1 burn-in scratch, fwd
__device__ float g_hpb[(BURN + 1) * H_DIM];          // chunk-1 burn-in scratch, bwd
__device__ float g_feats[T_LEN * TAGS];
__device__ float g_dump[64];                          // branchless-store sink

// ---------------- helpers -----------------------------------------------------
__device__ __forceinline__ float2 ldrg2(const float* p) {
    unsigned long long u;
    asm volatile("ld.relaxed.gpu.global.b64 %0, [%1];" : "=l"(u) : "l"(p));
    float2 v;
    v.x = __uint_as_float((unsigned)(u & 0xFFFFFFFFull));
    v.y = __uint_as_float((unsigned)(u >> 32));
    return v;
}
__device__ __forceinline__ void strg(float* p, float v) {
    asm volatile("st.relaxed.gpu.global.f32 [%0], %1;" :: "l"(p), "f"(v) : "memory");
}
__device__ __forceinline__ unsigned sm_u32(const void* p) {
    unsigned r;
    asm("{ .reg .u64 t; cvta.to.shared.u64 t, %1; cvt.u32.u64 %0, t; }"
        : "=r"(r) : "l"(p));
    return r;
}
__device__ __forceinline__ void ldsm4(unsigned r[4], unsigned addr) {
    asm volatile("ldmatrix.sync.aligned.m8n8.x4.shared.b16 {%0,%1,%2,%3}, [%4];"
                 : "=r"(r[0]), "=r"(r[1]), "=r"(r[2]), "=r"(r[3]) : "r"(addr));
}
__device__ __forceinline__ void mma16816(float d[4], const unsigned a[4],
                                         unsigned b0, unsigned b1) {
    asm volatile(
        "mma.sync.aligned.m16n8k16.row.col.f32.bf16.bf16.f32 "
        "{%0,%1,%2,%3}, {%4,%5,%6,%7}, {%8,%9}, {%0,%1,%2,%3};"
        : "+f"(d[0]), "+f"(d[1]), "+f"(d[2]), "+f"(d[3])
        : "r"(a[0]), "r"(a[1]), "r"(a[2]), "r"(a[3]), "r"(b0), "r"(b1));
}

// ---------------- dummy (launch-order shim so ncu captures recur_kernel) -------
__global__ void dummy_kernel() {}

// ---------------- gate GEMM: bf16 tensor cores + fused sentinel setup ----------
// Prologue: the 1024 blocks stripe-fill the h sentinel arrays (replaces the old
// setup_kernel; ~4 float4 stores per thread). GEMM completes before recur in
// stream order, so all fills are visible to the recurrence.
#define GPITCH 40

__global__ __launch_bounds__(256) void gemm_bf16(
    const int* __restrict__ sent, const float* __restrict__ embed,
    const float* __restrict__ Wf, const float* __restrict__ bf,
    const float* __restrict__ Wb, const float* __restrict__ bb,
    const float* __restrict__ h0)
{
    // ---- fused setup: sentinel/zero/h0 fills, grid-striped ----
    {
        const float4 s4 = make_float4(SENT, SENT, SENT, SENT);
        const float4 z4 = make_float4(0.f, 0.f, 0.f, 0.f);
        int gb = (blockIdx.z * gridDim.y + blockIdx.y) * gridDim.x + blockIdx.x;
        size_t gt = (size_t)gb * blockDim.x + threadIdx.x;
        const size_t NTH = (size_t)16 * 32 * 2 * 256;   // 262144 threads
        size_t nH4 = (size_t)T_LEN * H_DIM / 4;          // 524288
        float4* hsf4 = (float4*)(g_hsf + H_DIM);
        float4* hsb4 = (float4*)(g_hsb + H_DIM);
        for (size_t i = gt; i < nH4; i += NTH) { hsf4[i] = s4; hsb4[i] = s4; }
        if (gt < (size_t)(BURN * H_DIM / 4)) {
            ((float4*)(g_hpf + H_DIM))[gt] = s4;
            ((float4*)(g_hpb + H_DIM))[gt] = s4;
        }
        if (gt < H_DIM / 4) {
            ((float4*)g_hpf)[gt] = z4;
            ((float4*)g_hpb)[gt] = z4;
        }
        if (gt < H_DIM) {
            g_hsf[gt] = h0[gt];
            g_hsb[gt] = h0[H_DIM + gt];
        }
    }

    const int dir = blockIdx.z;
    const float* W    = dir ? Wb : Wf;
    const float* bias = dir ? bb : bf;
    float* G          = dir ? g_Gb : g_Gf;

    __shared__ __align__(16) unsigned short smA[128 * GPITCH];
    __shared__ __align__(16) unsigned short smB[128 * GPITCH];
    __shared__ int sRow[128];

    const int tid = threadIdx.x;
    const int m0 = blockIdx.y * 128;
    const int n0 = blockIdx.x * 128;

    if (tid < 128) {
        int t = m0 + tid;
        sRow[tid] = dir ? sent[T_LEN - 1 - t] : sent[t];
    }
    __syncthreads();

    const int srow = tid >> 1;
    const int sseg = tid & 1;
    const float* aSrc = embed + (size_t)sRow[srow] * E_DIM + sseg * 16;
    const float* bSrc = W + (size_t)(n0 + srow) * E_DIM + sseg * 16;
    unsigned short* aDst = &smA[srow * GPITCH + sseg * 16];
    unsigned short* bDst = &smB[srow * GPITCH + sseg * 16];

    const int warpId = tid >> 5;
    const int lane   = tid & 31;
    const int mbase  = (warpId & 3) * 32;
    const int nbase  = (warpId >> 2) * 64;
    const int quad   = lane >> 3;
    const int rl     = lane & 7;
    const unsigned smA0 = sm_u32(smA);
    const unsigned smB0 = sm_u32(smB);

    float d[2][8][4];
#pragma unroll
    for (int i = 0; i < 2; i++)
#pragma unroll
        for (int j = 0; j < 8; j++)
#pragma unroll
            for (int q = 0; q < 4; q++) d[i][j][q] = 0.f;

    for (int kt = 0; kt < E_DIM; kt += 32) {
        {
            float4 v0 = *(const float4*)(aSrc + kt);
            float4 v1 = *(const float4*)(aSrc + kt + 4);
            float4 v2 = *(const float4*)(aSrc + kt + 8);
            float4 v3 = *(const float4*)(aSrc + kt + 12);
            __nv_bfloat162 p[8];
            p[0] = __floats2bfloat162_rn(v0.x, v0.y);
            p[1] = __floats2bfloat162_rn(v0.z, v0.w);
            p[2] = __floats2bfloat162_rn(v1.x, v1.y);
            p[3] = __floats2bfloat162_rn(v1.z, v1.w);
            p[4] = __floats2bfloat162_rn(v2.x, v2.y);
            p[5] = __floats2bfloat162_rn(v2.z, v2.w);
            p[6] = __floats2bfloat162_rn(v3.x, v3.y);
            p[7] = __floats2bfloat162_rn(v3.z, v3.w);
            *(uint4*)(aDst)     = *(uint4*)&p[0];
            *(uint4*)(aDst + 8) = *(uint4*)&p[4];

            v0 = *(const float4*)(bSrc + kt);
            v1 = *(const float4*)(bSrc + kt + 4);
            v2 = *(const float4*)(bSrc + kt + 8);
            v3 = *(const float4*)(bSrc + kt + 12);
            p[0] = __floats2bfloat162_rn(v0.x, v0.y);
            p[1] = __floats2bfloat162_rn(v0.z, v0.w);
            p[2] = __floats2bfloat162_rn(v1.x, v1.y);
            p[3] = __floats2bfloat162_rn(v1.z, v1.w);
            p[4] = __floats2bfloat162_rn(v2.x, v2.y);
            p[5] = __floats2bfloat162_rn(v2.z, v2.w);
            p[6] = __floats2bfloat162_rn(v3.x, v3.y);
            p[7] = __floats2bfloat162_rn(v3.z, v3.w);
            *(uint4*)(bDst)     = *(uint4*)&p[0];
            *(uint4*)(bDst + 8) = *(uint4*)&p[4];
        }
        __syncthreads();

#pragma unroll
        for (int s = 0; s < 2; s++) {
            unsigned afr[2][4], bfr[4][4];
#pragma unroll
            for (int i = 0; i < 2; i++) {
                int row = mbase + i * 16 + rl + ((quad & 1) << 3);
                int col = s * 16 + ((quad & 2) << 2);
                ldsm4(afr[i], smA0 + 2 * (row * GPITCH + col));
            }
#pragma unroll
            for (int j = 0; j < 4; j++) {
                int row = nbase + j * 16 + rl + ((quad & 2) << 2);
                int col = s * 16 + ((quad & 1) << 3);
                ldsm4(bfr[j], smB0 + 2 * (row * GPITCH + col));
            }
#pragma unroll
            for (int i = 0; i < 2; i++)
#pragma unroll
                for (int j = 0; j < 4; j++) {
                    mma16816(d[i][2 * j],     afr[i], bfr[j][0], bfr[j][1]);
                    mma16816(d[i][2 * j + 1], afr[i], bfr[j][2], bfr[j][3]);
                }
        }
        __syncthreads();
    }

    const int gl = lane >> 2;
    const int lc = (lane & 3) * 2;
#pragma unroll
    for (int i = 0; i < 2; i++) {
        int r0 = m0 + mbase + i * 16 + gl;
        int r1 = r0 + 8;
#pragma unroll
        for (int jj = 0; jj < 8; jj++) {
            int col = n0 + nbase + jj * 8 + lc;
            float b0 = bias[col], b1 = bias[col + 1];
            float2 v0 = make_float2(d[i][jj][0] + b0, d[i][jj][1] + b1);
            float2 v1 = make_float2(d[i][jj][2] + b0, d[i][jj][3] + b1);
            *(float2*)(G + (size_t)r0 * G4H + col) = v0;
            *(float2*)(G + (size_t)r1 * G4H + col) = v1;
        }
    }
}

// ---------------- C=2 chunked recurrence (frozen from R15) ---------------------
__global__ __launch_bounds__(256, 2) void recur_kernel(
    const float* __restrict__ Whf, const float* __restrict__ Whb,
    const float* __restrict__ c0)
{
    const int tid  = threadIdx.x;
    const int bid  = blockIdx.x;
    const int dir   = bid >> 7;
    const int chunk = (bid >> 6) & 1;
    const int blk   = bid & 63;

    const float* Wh = dir ? Whb : Whf;
    const float* G  = dir ? g_Gb : g_Gf;
    float* hs       = dir ? g_hsb : g_hsf;
    float* priv     = dir ? g_hpb : g_hpf;

    const int t0 = chunk ? T1_OFF : 0;
    const int nS = NS_CHK;

    const int wid  = tid >> 5;       // warp = h segment 0..7
    const int lane = tid & 31;       // lane = row (gate*8 + unit)
    const int r = lane >> 3;         // gate 0..3
    const int u = lane & 7;          // unit 0..7
    const int j0 = blk * UPB;

    float w[64];
    {
        const float* wr = Wh + (size_t)(r * H_DIM + j0 + u) * H_DIM + 64 * wid;
#pragma unroll
        for (int q = 0; q < 16; q++) {
            float4 v = ((const float4*)wr)[q];
            w[4 * q + 0] = v.x; w[4 * q + 1] = v.y;
            w[4 * q + 2] = v.z; w[4 * q + 3] = v.w;
        }
    }

    float c = 0.f;
    if (wid == 0 && lane < UPB && chunk == 0) c = c0[dir * H_DIM + j0 + lane];

    __shared__ __align__(16) float shSeg[8][64];
    __shared__ float shP[2][8][33];

    const int goff = r * H_DIM + j0 + u;
    float gv = 0.f;

    for (int s = 0; s < nS; s++) {
        const int t = t0 + s;

        float gnext = 0.f;
        if (wid == 0) gnext = __ldg(G + (size_t)t * G4H + goff);

        if (wid == 0 && s > 0) {
            const float* Pp = &shP[(s + 1) & 1][0][lane];
            float sum = 0.f;
#pragma unroll
            for (int q = 0; q < 8; q++) sum += Pp[q * 33];
            float v = gv + sum;
            float xin = (r == 2) ? v : (0.5f * v);
            float th  = __tanhf(xin);
            float act = (r == 2) ? th : (0.5f * th + 0.5f);
            float ff = __shfl_sync(0xffffffffu, act,  8 + u);
            float gg = __shfl_sync(0xffffffffu, act, 16 + u);
            float oo = __shfl_sync(0xffffffffu, act, 24 + u);
            // branchless tail store (no BSSY on the hot path)
            c = ff * c + act * gg;
            float h = oo * __tanhf(c);
            float* outRow = (chunk && (s - 1) < BURN)
                          ? (priv + (size_t)s * H_DIM)
                          : (hs + (size_t)t * H_DIM);
            float* dst = (lane < UPB) ? (outRow + j0 + lane) : (g_dump + lane);
            strg(dst, h);
        }

        {
            const float* inRow = (chunk && s <= BURN)
                               ? (priv + (size_t)s * H_DIM)
                               : (hs + (size_t)t * H_DIM);
            const float* hp = inRow + 64 * wid + 2 * lane;
            float2 hv;
            if (s == 0) {
                hv = *(const float2*)hp;
            } else {
                hv = ldrg2(hp);
                while (hv.x == SENT || hv.y == SENT) {
                    float2 p0 = ldrg2(hp);
                    float2 p1 = ldrg2(hp);
                    hv = (p0.x != SENT && p0.y != SENT) ? p0 : p1;
                }
            }
            shSeg[wid][2 * lane]     = hv.x;
            shSeg[wid][2 * lane + 1] = hv.y;
        }
        __syncwarp();

        float a0 = 0.f, a1 = 0.f, a2 = 0.f, a3 = 0.f;
        const float* sp = shSeg[wid];
#pragma unroll
        for (int q = 0; q < 16; q++) {
            float4 h4 = *(const float4*)(sp + 4 * q);
            a0 = fmaf(w[4 * q + 0], h4.x, a0);
            a1 = fmaf(w[4 * q + 1], h4.y, a1);
            a2 = fmaf(w[4 * q + 2], h4.z, a2);
            a3 = fmaf(w[4 * q + 3], h4.w, a3);
        }
        shP[s & 1][wid][lane] = (a0 + a1) + (a2 + a3);

        __syncthreads();
        gv = gnext;
    }

    if (wid == 0) {
        const float* Pp = &shP[(nS + 1) & 1][0][lane];
        float sum = 0.f;
#pragma unroll
        for (int q = 0; q < 8; q++) sum += Pp[q * 33];
        float v = gv + sum;
        float xin = (r == 2) ? v : (0.5f * v);
        float th  = __tanhf(xin);
        float act = (r == 2) ? th : (0.5f * th + 0.5f);
        float ff = __shfl_sync(0xffffffffu, act,  8 + u);
        float gg = __shfl_sync(0xffffffffu, act, 16 + u);
        float oo = __shfl_sync(0xffffffffu, act, 24 + u);
        if (lane < UPB) {
            c = ff * c + act * gg;
            float h = oo * __tanhf(c);
            strg(hs + (size_t)(t0 + nS) * H_DIM + j0 + lane, h);
        }
    }
}

// ---------------- output projection: feats[t][tag] ---------------------------
__global__ void feats_kernel(const float* __restrict__ Wout,
                             const float* __restrict__ bout)
{
    const int t = blockIdx.x;
    const int w = threadIdx.x >> 5;
    const int lane = threadIdx.x & 31;
    const float* hf = g_hsf + (size_t)(t + 1) * H_DIM;
    const float* hb = g_hsb + (size_t)(T_LEN - t) * H_DIM;
    const float* wr = Wout + w * (2 * H_DIM);

    float sum = 0.f;
#pragma unroll 4
    for (int e = lane; e < H_DIM; e += 32) sum = fmaf(hf[e], wr[e], sum);
#pragma unroll 4
    for (int e = lane; e < H_DIM; e += 32) sum = fmaf(hb[e], wr[H_DIM + e], sum);

    sum += __shfl_xor_sync(0xffffffffu, sum, 16);
    sum += __shfl_xor_sync(0xffffffffu, sum, 8);
    sum += __shfl_xor_sync(0xffffffffu, sum, 4);
    sum += __shfl_xor_sync(0xffffffffu, sum, 2);
    sum += __shfl_xor_sync(0xffffffffu, sum, 1);
    if (lane == 0) g_feats[t * TAGS + w] = sum + bout[w];
}

// ---------------- Viterbi decode: branchless inner loop (frozen from R15) ------
__global__ void viterbi_kernel(const float* __restrict__ trans,
                               float* __restrict__ out, int out_size)
{
    extern __shared__ float sFeats[];                 // 80 KB
    __shared__ unsigned char sBp[T_LEN * TAGS];       // 20 KB
    __shared__ unsigned char sDump[32];               // branchless-store sink

    const int tid = threadIdx.x;
    for (int i = tid; i < T_LEN * TAGS; i += blockDim.x) sFeats[i] = g_feats[i];
    __syncthreads();

    if (tid < 32) {
        const int lane = tid;
        const bool valid = (lane < TAGS);
        float tr[TAGS];
#pragma unroll
        for (int p = 0; p < TAGS; p++) tr[p] = 0.f;
        if (valid)
#pragma unroll
            for (int p = 0; p < TAGS; p++) tr[p] = trans[lane * TAGS + p];

        float fv = (lane == START_TAG) ? 0.f : -10000.0f;
        if (!valid) fv = -1e30f;

        const int featLane = valid ? lane : 0;

        for (int t = 0; t < T_LEN; t += 2) {
#pragma unroll
            for (int uu = 0; uu < 2; uu++) {
                int tt = t + uu;
                float f0 = __shfl_sync(0xffffffffu, fv, 0);
                float f1 = __shfl_sync(0xffffffffu, fv, 1);
                float f2 = __shfl_sync(0xffffffffu, fv, 2);
                float f3 = __shfl_sync(0xffffffffu, fv, 3);
                float f4 = __shfl_sync(0xffffffffu, fv, 4);
                float s0 = f0 + tr[0], s1 = f1 + tr[1], s2 = f2 + tr[2];
                float s3 = f3 + tr[3], s4 = f4 + tr[4];
                float m01 = fmaxf(s0, s1); int b01 = (s1 > s0) ? 1 : 0;
                float m23 = fmaxf(s2, s3); int b23 = (s3 > s2) ? 3 : 2;
                float m03 = fmaxf(m01, m23); int b03 = (m23 > m01) ? b23 : b01;
                float best = fmaxf(m03, s4); int bp = (s4 > m03) ? 4 : b03;
                float feat = sFeats[tt * TAGS + featLane];
                fv = valid ? (best + feat) : fv;
                unsigned char* bpPtr = valid ? &sBp[tt * TAGS + lane]
                                             : &sDump[lane];
                *bpPtr = (unsigned char)bp;
            }
        }

        float term = valid ? (fv + trans[STOP_TAG * TAGS + lane]) : -1e30f;
        float t0 = __shfl_sync(0xffffffffu, term, 0);
        float t1 = __shfl_sync(0xffffffffu, term, 1);
        float t2 = __shfl_sync(0xffffffffu, term, 2);
        float t3 = __shfl_sync(0xffffffffu, term, 3);
        float t4 = __shfl_sync(0xffffffffu, term, 4);

        if (lane == 0) {
            float best = t0; int bl = 0;
            if (t1 > best) { best = t1; bl = 1; }
            if (t2 > best) { best = t2; bl = 2; }
            if (t3 > best) { best = t3; bl = 3; }
            if (t4 > best) { best = t4; bl = 4; }

            int base = (out_size > T_LEN) ? 1 : 0;
            if (base == 1 && out_size >= 1) out[0] = best;

            int y = bl;
            int idx = base + (T_LEN - 1);
            if (idx < out_size) out[idx] = (float)y;
            for (int t = T_LEN - 1; t >= 1; t--) {
                y = sBp[t * TAGS + y];
                idx = base + (t - 1);
                if (idx < out_size) out[idx] = (float)y;
            }
        }
    }
}

// ---------------- launcher ---------------------------------------------------
// Launch order puts recur_kernel at position 4 — the slot the ncu capture has
// consistently landed on — so the dominant kernel finally gets profiled.
extern "C" void kernel_launch(void* const* d_in, const int* in_sizes, int n_in,
                              void* d_out, int out_size)
{
    const int*   sentence = (const int*)  d_in[0];
    const float* embed    = (const float*)d_in[1];
    const float* W_ih_f   = (const float*)d_in[2];
    const float* W_hh_f   = (const float*)d_in[3];
    const float* b_f      = (const float*)d_in[4];
    const float* W_ih_b   = (const float*)d_in[5];
    const float* W_hh_b   = (const float*)d_in[6];
    const float* b_b      = (const float*)d_in[7];
    const float* h0       = (const float*)d_in[8];
    const float* c0       = (const float*)d_in[9];
    const float* W_out    = (const float*)d_in[10];
    const float* b_out    = (const float*)d_in[11];
    const float* trans    = (const float*)d_in[12];
    float* out = (float*)d_out;

    gemm_bf16<<<dim3(16, 32, 2), 256>>>(sentence, embed,      // #1 (incl. setup)
                                        W_ih_f, b_f, W_ih_b, b_b, h0);
    dummy_kernel<<<1, 32>>>();                                // #2 (shim)
    dummy_kernel<<<1, 32>>>();                                // #3 (shim)
    recur_kernel<<<256, 256>>>(W_hh_f, W_hh_b, c0);           // #4 <- profiled
    feats_kernel<<<T_LEN, TAGS * 32>>>(W_out, b_out);         // #5
    cudaFuncSetAttribute(viterbi_kernel,
                         cudaFuncAttributeMaxDynamicSharedMemorySize,
                         T_LEN * TAGS * sizeof(float));
    viterbi_kernel<<<1, 1024, T_LEN * TAGS * sizeof(float)>>>(trans, out, out_size);
}